// round 5
// baseline (speedup 1.0000x reference)
#include <cuda_runtime.h>

#define NB 2
#define NC 96
#define ND 40
#define HW 1600
#define SP 64000   // 40*40*40

// ---------------- scratch (no allocs allowed) ----------------
__device__ float g_buf1[NB*NC*SP];
__device__ float g_buf2[NB*NC*SP];
__device__ float g_xmod[NB*NC*SP];
__device__ float g_qkv [NB*3*NC*SP];
__device__ float g_osum[NB*NC*SP];
__device__ float g_stats[NB*NC*2];
__device__ float g_wt[NC*NC*27];   // conv3 weights as [ci][tap][co]

// ---------------- packed fp32x2 helpers ----------------
__device__ __forceinline__ void ffma2(unsigned long long &acc, unsigned long long w, unsigned long long x) {
    asm("fma.rn.f32x2 %0, %1, %2, %0;" : "+l"(acc) : "l"(w), "l"(x));
}
__device__ __forceinline__ unsigned long long bcast2(float x) {
    unsigned long long r;
    asm("mov.b64 %0, {%1, %1};" : "=l"(r) : "f"(x));
    return r;
}
__device__ __forceinline__ float2 unpack2(unsigned long long v) {
    float2 r;
    asm("mov.b64 {%0, %1}, %2;" : "=f"(r.x), "=f"(r.y) : "l"(v));
    return r;
}

// ---------------- weight transpose for conv3 ----------------
__global__ void k_wt(const float* __restrict__ w) {
    int idx = blockIdx.x*256 + threadIdx.x;
    if (idx >= NC*NC*27) return;
    int co  = idx % NC;
    int tap = (idx/NC) % 27;
    int ci  = idx/(NC*27);
    g_wt[idx] = w[(co*NC + ci)*27 + tap];
}

// ---------------- conv 3x3x3 circular (pos_emb -> g_buf1) ----------------
// block: (b, d, 4 h-rows). out tile: 96 co x 4 h x 40 w. 256 thr:
// 8 co-groups (12 co each, paired into 6 f32x2) x 32 s-groups (5 w each).
__global__ void __launch_bounds__(256) k_conv3(const float* __restrict__ x, const float* __restrict__ bias) {
    __shared__ __align__(16) float s_in[2*756];     // [ci2][dd3][hh6][ww42]
    __shared__ __align__(16) float s_w [2*2592];    // [ci2][tap27][co96]
    int b = blockIdx.z, d = blockIdx.y, h0 = blockIdx.x*4;
    int t = threadIdx.x;
    int sg = t & 31, cg = t >> 5;
    int s0 = sg*5, hp = s0/40, w0 = s0%40;
    int co0 = cg*12;

    unsigned long long acc[6][5];
    #pragma unroll
    for (int p=0;p<6;p++)
        #pragma unroll
        for (int j=0;j<5;j++) acc[p][j] = 0ull;

    for (int ci0=0; ci0<NC; ci0+=2) {
        __syncthreads();
        for (int idx=t; idx<2*756; idx+=256) {
            int ci = idx/756, r = idx%756;
            int dd = r/252, r2 = r%252, hh = r2/42, ww = r2%42;
            int gd = d+dd-1;  if (gd<0) gd+=ND; else if (gd>=ND) gd-=ND;
            int gh = h0+hh-1; if (gh<0) gh+=ND; else if (gh>=ND) gh-=ND;
            int gw = ww-1;    if (gw<0) gw+=ND; else if (gw>=ND) gw-=ND;
            s_in[idx] = x[(size_t)(b*NC+ci0+ci)*SP + gd*HW + gh*ND + gw];
        }
        for (int idx=t; idx<2*2592; idx+=256)
            s_w[idx] = g_wt[ci0*2592 + idx];
        __syncthreads();

        #pragma unroll
        for (int ci=0; ci<2; ci++) {
            #pragma unroll
            for (int kd=0; kd<3; kd++) {
                #pragma unroll
                for (int kh=0; kh<3; kh++) {
                    float xr[7];
                    const float* xin = &s_in[ci*756 + kd*252 + (hp+kh)*42 + w0];
                    #pragma unroll
                    for (int j=0;j<7;j++) xr[j] = xin[j];
                    #pragma unroll
                    for (int kw=0; kw<3; kw++) {
                        const unsigned long long* wp =
                            (const unsigned long long*)&s_w[(ci*27 + kd*9 + kh*3 + kw)*NC + co0];
                        unsigned long long wv[6];
                        #pragma unroll
                        for (int p=0;p<6;p++) wv[p] = wp[p];
                        #pragma unroll
                        for (int j=0;j<5;j++) {
                            unsigned long long xb = bcast2(xr[kw+j]);
                            #pragma unroll
                            for (int p=0;p<6;p++) ffma2(acc[p][j], wv[p], xb);
                        }
                    }
                }
            }
        }
    }
    int h = h0 + hp;
    #pragma unroll
    for (int p=0;p<6;p++) {
        int c = co0 + 2*p;
        float b0 = bias[c], b1 = bias[c+1];
        #pragma unroll
        for (int j=0;j<5;j++) {
            float2 v = unpack2(acc[p][j]);
            size_t off = (size_t)(b*NC+c)*SP + d*HW + h*ND + (w0+j);
            g_buf1[off]      = v.x + b0;
            g_buf1[off + SP] = v.y + b1;
        }
    }
}

// ---------------- instance-norm stats per (b,c) ----------------
__global__ void __launch_bounds__(256) k_stats(const float* __restrict__ x) {
    __shared__ double ss[256], ss2[256];
    int bc = blockIdx.x, t = threadIdx.x;
    const float* p = x + (size_t)bc*SP;
    double s=0.0, s2=0.0;
    for (int i=t; i<SP; i+=256) { double v = p[i]; s += v; s2 += v*v; }
    ss[t]=s; ss2[t]=s2; __syncthreads();
    for (int o=128;o>0;o>>=1){ if(t<o){ss[t]+=ss[t+o]; ss2[t]+=ss2[t+o];} __syncthreads(); }
    if (t==0) {
        double mu  = ss[0]/(double)SP;
        double var = ss2[0]/(double)SP - mu*mu;
        g_stats[bc*2]   = (float)mu;
        g_stats[bc*2+1] = (float)(1.0/sqrt(var + 1e-5));
    }
}

// ---------------- normalize + exact gelu ----------------
__global__ void __launch_bounds__(256) k_ngelu(const float* __restrict__ in, float* __restrict__ out) {
    int bc  = blockIdx.x / 250;
    int rem = blockIdx.x % 250;
    size_t i = (size_t)bc*SP + rem*256 + threadIdx.x;
    float v = (in[i] - g_stats[bc*2]) * g_stats[bc*2+1];
    out[i] = 0.5f * v * (1.0f + erff(v * 0.70710678118654752f));
}

// ---------------- conv1x1 GEMM: out[b,co,s] = sum_ci W[co,ci]*in[b,ci,s] + bias ----------------
// ACT 0: plain.  ACT 1: out = sigmoid(res) * aux  (mod gate fused with x multiply)
template<int ACT>
__global__ void __launch_bounds__(256) k_gemm(const float* __restrict__ in, const float* __restrict__ W,
                                              const float* __restrict__ bias, float* __restrict__ out,
                                              int OC, const float* __restrict__ aux) {
    __shared__ __align__(16) float s_x[32*128];
    __shared__ __align__(16) float s_w[32*100];   // [ci][co] padded
    int b = blockIdx.z, s0 = blockIdx.x*128, co0 = blockIdx.y*96;
    int t = threadIdx.x, tx = t & 31, ty = t >> 5;

    unsigned long long acc[6][4];
    #pragma unroll
    for (int p=0;p<6;p++)
        #pragma unroll
        for (int j=0;j<4;j++) acc[p][j] = 0ull;

    for (int ci0=0; ci0<NC; ci0+=32) {
        __syncthreads();
        for (int idx=t; idx<4096; idx+=256) {
            int ci = idx>>7, s = idx&127;
            s_x[idx] = in[(size_t)(b*NC+ci0+ci)*SP + s0 + s];
        }
        for (int idx=t; idx<3072; idx+=256) {
            int ci = idx & 31, co = idx >> 5;
            s_w[ci*100 + co] = W[(co0+co)*NC + ci0 + ci];
        }
        __syncthreads();
        #pragma unroll 4
        for (int ci=0; ci<32; ci++) {
            float4 xv = *(const float4*)&s_x[ci*128 + tx*4];
            unsigned long long xb[4] = { bcast2(xv.x), bcast2(xv.y), bcast2(xv.z), bcast2(xv.w) };
            const unsigned long long* wp = (const unsigned long long*)&s_w[ci*100 + ty*12];
            #pragma unroll
            for (int p=0;p<6;p++) {
                unsigned long long wv = wp[p];
                #pragma unroll
                for (int j=0;j<4;j++) ffma2(acc[p][j], wv, xb[j]);
            }
        }
    }
    #pragma unroll
    for (int p=0;p<6;p++) {
        int c = co0 + ty*12 + 2*p;
        float b0 = bias[c], b1 = bias[c+1];
        float2 v[4];
        #pragma unroll
        for (int j=0;j<4;j++) { v[j] = unpack2(acc[p][j]); v[j].x += b0; v[j].y += b1; }
        size_t o0 = (size_t)(b*OC + c)*SP + s0 + tx*4;
        float4 r0, r1;
        if (ACT == 0) {
            r0 = make_float4(v[0].x, v[1].x, v[2].x, v[3].x);
            r1 = make_float4(v[0].y, v[1].y, v[2].y, v[3].y);
        } else {
            size_t a0 = (size_t)(b*NC + c)*SP + s0 + tx*4;
            float m0[4], m1[4];
            #pragma unroll
            for (int j=0;j<4;j++) {
                m0[j] = aux[a0+j]      * (1.f/(1.f+expf(-v[j].x)));
                m1[j] = aux[a0+SP+j]   * (1.f/(1.f+expf(-v[j].y)));
            }
            r0 = make_float4(m0[0], m0[1], m0[2], m0[3]);
            r1 = make_float4(m1[0], m1[1], m1[2], m1[3]);
        }
        *(float4*)&out[o0]      = r0;
        *(float4*)&out[o0 + SP] = r1;
    }
}

// ---------------- axial attention: one sequence (L=40) per block ----------------
// Rotation skipped (orthogonal, cancels in q.k); pos_attn skipped (constant per
// softmax row). q,k,v taken from the shared QKV projection.
__global__ void __launch_bounds__(160) k_attn(int axis, int accum) {
    __shared__ __align__(16) float sq[3840], sk[3840], sv[3840];
    int blk = blockIdx.x;
    int b = blk / 1600, r = blk % 1600, a1 = r/40, a2 = r%40;
    int base, lst;
    if (axis == 0)      { base = a1*ND + a2;     lst = HW; }   // seq over d, (a1,a2)=(h,w)
    else if (axis == 1) { base = a1*HW + a2;     lst = ND; }   // seq over h, (a1,a2)=(d,w)
    else                { base = a1*HW + a2*ND;  lst = 1;  }   // seq over w, (a1,a2)=(d,h)
    int t = threadIdx.x;

    for (int idx=t; idx<11520; idx+=160) {
        int c = idx % 96;
        int l = (idx/96) % 40;
        int which = idx / 3840;
        float v = g_qkv[(size_t)(b*288 + which*96 + c)*SP + base + l*lst];
        float* dst = (which==0) ? sq : ((which==1) ? sk : sv);
        dst[l*96 + c] = v;
    }
    __syncthreads();

    int h = t/40, i = t%40;        // head, query token
    float4 q[6];
    #pragma unroll
    for (int u=0;u<6;u++) q[u] = *(const float4*)&sq[i*96 + h*24 + u*4];

    const float scale = 0.20412414523193154f;  // 1/sqrt(24)
    float S[40];
    float mx = -1e30f;
    #pragma unroll
    for (int j=0;j<40;j++) {
        const float4* kp = (const float4*)&sk[j*96 + h*24];
        float s = 0.f;
        #pragma unroll
        for (int u=0;u<6;u++) {
            float4 kv = kp[u];
            s += q[u].x*kv.x + q[u].y*kv.y + q[u].z*kv.z + q[u].w*kv.w;
        }
        s *= scale;
        S[j] = s;
        mx = fmaxf(mx, s);
    }
    float sum = 0.f;
    #pragma unroll
    for (int j=0;j<40;j++) { S[j] = expf(S[j]-mx); sum += S[j]; }
    float inv = 1.f/sum;

    float4 o[6];
    #pragma unroll
    for (int u=0;u<6;u++) o[u] = make_float4(0.f,0.f,0.f,0.f);
    #pragma unroll
    for (int j=0;j<40;j++) {
        float p = S[j]*inv;
        const float4* vp = (const float4*)&sv[j*96 + h*24];
        #pragma unroll
        for (int u=0;u<6;u++) {
            float4 vv = vp[u];
            o[u].x += p*vv.x; o[u].y += p*vv.y; o[u].z += p*vv.z; o[u].w += p*vv.w;
        }
    }
    size_t ob = (size_t)(b*NC + h*24)*SP + base + (size_t)i*lst;
    #pragma unroll
    for (int u=0;u<6;u++) {
        float comp[4] = {o[u].x, o[u].y, o[u].z, o[u].w};
        #pragma unroll
        for (int m=0;m<4;m++) {
            size_t a = ob + (size_t)(u*4+m)*SP;
            if (accum) g_osum[a] += comp[m];
            else       g_osum[a]  = comp[m];
        }
    }
}

// ---------------- launch ----------------
extern "C" void kernel_launch(void* const* d_in, const int* in_sizes, int n_in,
                              void* d_out, int out_size) {
    const float* x      = (const float*)d_in[0];
    const float* pos    = (const float*)d_in[1];
    const float* qkv_w  = (const float*)d_in[2];
    const float* qkv_b  = (const float*)d_in[3];
    const float* lp1_w  = (const float*)d_in[4];
    const float* lp1_b  = (const float*)d_in[5];
    const float* lp2_w  = (const float*)d_in[6];
    const float* lp2_b  = (const float*)d_in[7];
    const float* mod1_w = (const float*)d_in[8];
    const float* mod1_b = (const float*)d_in[9];
    const float* mod2_w = (const float*)d_in[10];
    const float* mod2_b = (const float*)d_in[11];
    // d_in[12..16]: pa_w, pa_b, R6_d, R6_h, R6_w — mathematically unused (see analysis)
    const float* proj_w = (const float*)d_in[17];
    const float* proj_b = (const float*)d_in[18];
    float* out = (float*)d_out;

    float *buf1, *buf2, *xmod, *qkv, *osum;
    cudaGetSymbolAddress((void**)&buf1, g_buf1);
    cudaGetSymbolAddress((void**)&buf2, g_buf2);
    cudaGetSymbolAddress((void**)&xmod, g_xmod);
    cudaGetSymbolAddress((void**)&qkv,  g_qkv);
    cudaGetSymbolAddress((void**)&osum, g_osum);

    // conv3 weight relayout
    k_wt<<<(NC*NC*27 + 255)/256, 256>>>(lp1_w);
    // local path: conv3 -> IN -> gelu -> conv1x1
    k_conv3<<<dim3(10,40,2), 256>>>(pos, lp1_b);
    k_stats<<<NB*NC, 256>>>(buf1);
    k_ngelu<<<NB*NC*250, 256>>>(buf1, buf2);
    k_gemm<0><<<dim3(500,1,2), 256>>>(buf2, lp2_w, lp2_b, buf1, 96, nullptr);   // local
    // mod path: conv1x1 -> IN -> gelu -> conv1x1 -> sigmoid, fused x*mod
    k_gemm<0><<<dim3(500,1,2), 256>>>(buf1, mod1_w, mod1_b, buf2, 96, nullptr);
    k_stats<<<NB*NC, 256>>>(buf2);
    k_ngelu<<<NB*NC*250, 256>>>(buf2, buf1);
    k_gemm<1><<<dim3(500,1,2), 256>>>(buf1, mod2_w, mod2_b, xmod, 96, x);       // x_mod
    // shared QKV projection (axis-independent)
    k_gemm<0><<<dim3(500,3,2), 256>>>(xmod, qkv_w, qkv_b, qkv, 288, nullptr);
    // three axial attentions, accumulated
    k_attn<<<3200, 160>>>(0, 0);
    k_attn<<<3200, 160>>>(1, 1);
    k_attn<<<3200, 160>>>(2, 1);
    // output projection
    k_gemm<0><<<dim3(500,1,2), 256>>>(osum, proj_w, proj_b, out, 96, nullptr);
}

// round 6
// speedup vs baseline: 1.2476x; 1.2476x over previous
#include <cuda_runtime.h>
#include <math.h>

#define NB 2
#define NC 96
#define ND 40
#define HW 1600
#define SP 64000   // 40*40*40

// ---------------- scratch (no allocs allowed) ----------------
__device__ float g_buf1[NB*NC*SP];
__device__ float g_buf2[NB*NC*SP];
__device__ float g_xmod[NB*NC*SP];
__device__ float g_qkv [NB*3*4*SP*24];   // [b][which][head][S][24]
__device__ float g_osum[NB*4*SP*24];     // [b][head][S][24]
__device__ float g_stats[NB*NC*2];
__device__ float g_wt[NC*NC*27];         // conv3 weights as [ci][tap][co]

// ---------------- packed fp32x2 helpers ----------------
__device__ __forceinline__ void ffma2(unsigned long long &acc, unsigned long long w, unsigned long long x) {
    asm("fma.rn.f32x2 %0, %1, %2, %0;" : "+l"(acc) : "l"(w), "l"(x));
}
__device__ __forceinline__ unsigned long long bcast2(float x) {
    unsigned long long r;
    asm("mov.b64 %0, {%1, %1};" : "=l"(r) : "f"(x));
    return r;
}
__device__ __forceinline__ float2 unpack2(unsigned long long v) {
    float2 r;
    asm("mov.b64 {%0, %1}, %2;" : "=f"(r.x), "=f"(r.y) : "l"(v));
    return r;
}

// ---------------- weight transpose for conv3 ----------------
__global__ void k_wt(const float* __restrict__ w) {
    int idx = blockIdx.x*256 + threadIdx.x;
    if (idx >= NC*NC*27) return;
    int co  = idx % NC;
    int tap = (idx/NC) % 27;
    int ci  = idx/(NC*27);
    g_wt[idx] = w[(co*NC + ci)*27 + tap];
}

// ---------------- conv 3x3x3 circular (pos_emb -> g_buf1), ci-chunk 3 ----------------
__global__ void __launch_bounds__(256) k_conv3(const float* __restrict__ x, const float* __restrict__ bias) {
    __shared__ __align__(16) float s_in[3*756];     // [ci3][dd3][hh6][ww42]
    __shared__ __align__(16) float s_w [3*2592];    // [ci3][tap27][co96]
    int b = blockIdx.z, d = blockIdx.y, h0 = blockIdx.x*4;
    int t = threadIdx.x;
    int sg = t & 31, cg = t >> 5;
    int s0 = sg*5, hp = s0/40, w0 = s0%40;
    int co0 = cg*12;

    unsigned long long acc[6][5];
    #pragma unroll
    for (int p=0;p<6;p++)
        #pragma unroll
        for (int j=0;j<5;j++) acc[p][j] = 0ull;

    for (int ci0=0; ci0<NC; ci0+=3) {
        __syncthreads();
        for (int idx=t; idx<3*756; idx+=256) {
            int ci = idx/756, r = idx%756;
            int dd = r/252, r2 = r%252, hh = r2/42, ww = r2%42;
            int gd = d+dd-1;  if (gd<0) gd+=ND; else if (gd>=ND) gd-=ND;
            int gh = h0+hh-1; if (gh<0) gh+=ND; else if (gh>=ND) gh-=ND;
            int gw = ww-1;    if (gw<0) gw+=ND; else if (gw>=ND) gw-=ND;
            s_in[idx] = x[(size_t)(b*NC+ci0+ci)*SP + gd*HW + gh*ND + gw];
        }
        for (int idx=t; idx<3*2592; idx+=256)
            s_w[idx] = g_wt[ci0*2592 + idx];
        __syncthreads();

        #pragma unroll
        for (int ci=0; ci<3; ci++) {
            #pragma unroll
            for (int kd=0; kd<3; kd++) {
                #pragma unroll
                for (int kh=0; kh<3; kh++) {
                    float xr[7];
                    const float* xin = &s_in[ci*756 + kd*252 + (hp+kh)*42 + w0];
                    #pragma unroll
                    for (int j=0;j<7;j++) xr[j] = xin[j];
                    #pragma unroll
                    for (int kw=0; kw<3; kw++) {
                        const unsigned long long* wp =
                            (const unsigned long long*)&s_w[(ci*27 + kd*9 + kh*3 + kw)*NC + co0];
                        unsigned long long wv[6];
                        #pragma unroll
                        for (int p=0;p<6;p++) wv[p] = wp[p];
                        #pragma unroll
                        for (int j=0;j<5;j++) {
                            unsigned long long xb = bcast2(xr[kw+j]);
                            #pragma unroll
                            for (int p=0;p<6;p++) ffma2(acc[p][j], wv[p], xb);
                        }
                    }
                }
            }
        }
    }
    int h = h0 + hp;
    #pragma unroll
    for (int p=0;p<6;p++) {
        int c = co0 + 2*p;
        float b0 = bias[c], b1 = bias[c+1];
        #pragma unroll
        for (int j=0;j<5;j++) {
            float2 v = unpack2(acc[p][j]);
            size_t off = (size_t)(b*NC+c)*SP + d*HW + h*ND + (w0+j);
            g_buf1[off]      = v.x + b0;
            g_buf1[off + SP] = v.y + b1;
        }
    }
}

// ---------------- instance-norm stats per (b,c) ----------------
__global__ void __launch_bounds__(256) k_stats(const float* __restrict__ x) {
    __shared__ double ss[256], ss2[256];
    int bc = blockIdx.x, t = threadIdx.x;
    const float* p = x + (size_t)bc*SP;
    double s=0.0, s2=0.0;
    for (int i=t; i<SP; i+=256) { double v = p[i]; s += v; s2 += v*v; }
    ss[t]=s; ss2[t]=s2; __syncthreads();
    for (int o=128;o>0;o>>=1){ if(t<o){ss[t]+=ss[t+o]; ss2[t]+=ss2[t+o];} __syncthreads(); }
    if (t==0) {
        double mu  = ss[0]/(double)SP;
        double var = ss2[0]/(double)SP - mu*mu;
        g_stats[bc*2]   = (float)mu;
        g_stats[bc*2+1] = (float)(1.0/sqrt(var + 1e-5));
    }
}

// ---------------- fused conv1x1 GEMM ----------------
// IN_MODE:  0 = plain [b][c][S]   1 = instance-norm + exact gelu on load
//           2 = head layout [b][h][S][24] (proj reading attention output)
// OUT_MODE: 0 = plain [b][c][S]   1 = sigmoid(res)*aux (mod gate fused with x)
//           2 = QKV head layout [b][which][h][S][24], which = blockIdx.y
template<int IN_MODE, int OUT_MODE>
__global__ void __launch_bounds__(256) k_gemm(const float* __restrict__ in, const float* __restrict__ W,
                                              const float* __restrict__ bias, float* __restrict__ out,
                                              const float* __restrict__ aux) {
    __shared__ __align__(16) float s_mem[12288];   // 48KB: s_x[4096] + s_w[3200], reused as s_out[96*128]
    float* s_x = s_mem;
    float* s_w = s_mem + 4096;
    int b = blockIdx.z, s0 = blockIdx.x*128, grp = blockIdx.y;
    int co0 = grp*96;
    int t = threadIdx.x, tx = t & 31, ty = t >> 5;

    unsigned long long acc[6][4];
    #pragma unroll
    for (int p=0;p<6;p++)
        #pragma unroll
        for (int j=0;j<4;j++) acc[p][j] = 0ull;

    if constexpr (IN_MODE == 2) {
        for (int h4=0; h4<4; h4++) {
            __syncthreads();
            for (int idx=t; idx<3072; idx+=256) {
                int s = idx/24, hd = idx%24;
                s_x[hd*132 + s] = in[((size_t)(b*4+h4)*SP + s0 + s)*24 + hd];
            }
            for (int idx=t; idx<2304; idx+=256) {
                int co = idx/24, ci = idx%24;
                s_w[ci*100 + co] = W[(co0+co)*NC + h4*24 + ci];
            }
            __syncthreads();
            #pragma unroll 4
            for (int ci=0; ci<24; ci++) {
                float4 xv = *(const float4*)&s_x[ci*132 + tx*4];
                unsigned long long xb[4] = { bcast2(xv.x), bcast2(xv.y), bcast2(xv.z), bcast2(xv.w) };
                const unsigned long long* wp = (const unsigned long long*)&s_w[ci*100 + ty*12];
                #pragma unroll
                for (int p=0;p<6;p++) {
                    unsigned long long wv = wp[p];
                    #pragma unroll
                    for (int j=0;j<4;j++) ffma2(acc[p][j], wv, xb[j]);
                }
            }
        }
    } else {
        for (int ci0=0; ci0<NC; ci0+=32) {
            __syncthreads();
            for (int idx=t; idx<4096; idx+=256) {
                int ci = idx>>7, s = idx&127;
                float v = in[(size_t)(b*NC+ci0+ci)*SP + s0 + s];
                if constexpr (IN_MODE == 1) {
                    int bc = b*NC+ci0+ci;
                    v = (v - g_stats[bc*2]) * g_stats[bc*2+1];
                    v = 0.5f * v * (1.0f + erff(v * 0.70710678118654752f));
                }
                s_x[idx] = v;
            }
            for (int idx=t; idx<3072; idx+=256) {
                int ci = idx & 31, co = idx >> 5;
                s_w[ci*100 + co] = W[(co0+co)*NC + ci0 + ci];
            }
            __syncthreads();
            #pragma unroll 4
            for (int ci=0; ci<32; ci++) {
                float4 xv = *(const float4*)&s_x[ci*128 + tx*4];
                unsigned long long xb[4] = { bcast2(xv.x), bcast2(xv.y), bcast2(xv.z), bcast2(xv.w) };
                const unsigned long long* wp = (const unsigned long long*)&s_w[ci*100 + ty*12];
                #pragma unroll
                for (int p=0;p<6;p++) {
                    unsigned long long wv = wp[p];
                    #pragma unroll
                    for (int j=0;j<4;j++) ffma2(acc[p][j], wv, xb[j]);
                }
            }
        }
    }

    // epilogue: unpack to float4 rows (s-major) with bias
    float4 r0[6], r1[6];
    #pragma unroll
    for (int p=0;p<6;p++) {
        int c = ty*12 + 2*p;
        float b0 = bias[co0 + c], b1 = bias[co0 + c + 1];
        float2 v[4];
        #pragma unroll
        for (int j=0;j<4;j++) { v[j] = unpack2(acc[p][j]); v[j].x += b0; v[j].y += b1; }
        r0[p] = make_float4(v[0].x, v[1].x, v[2].x, v[3].x);
        r1[p] = make_float4(v[0].y, v[1].y, v[2].y, v[3].y);
    }

    if constexpr (OUT_MODE == 2) {
        __syncthreads();                  // s_x/s_w dead, reuse as s_out[96 co][128 s]
        float* s_out = s_mem;
        #pragma unroll
        for (int p=0;p<6;p++) {
            int c = ty*12 + 2*p;
            *(float4*)&s_out[c*128 + tx*4]     = r0[p];
            *(float4*)&s_out[(c+1)*128 + tx*4] = r1[p];
        }
        __syncthreads();
        float* ob = out + ((size_t)(b*3 + grp)*4)*SP*24;
        for (int f=t; f<3072; f+=256) {
            int h = f/768, rem = f%768, s = rem/6, u = rem%6;
            float4 r;
            r.x = s_out[(h*24+u*4+0)*128 + s];
            r.y = s_out[(h*24+u*4+1)*128 + s];
            r.z = s_out[(h*24+u*4+2)*128 + s];
            r.w = s_out[(h*24+u*4+3)*128 + s];
            *(float4*)&ob[((size_t)h*SP + s0 + s)*24 + u*4] = r;
        }
    } else {
        #pragma unroll
        for (int p=0;p<6;p++) {
            int c = ty*12 + 2*p;
            size_t o0 = (size_t)(b*NC + c)*SP + s0 + tx*4;
            if constexpr (OUT_MODE == 0) {
                *(float4*)&out[o0]      = r0[p];
                *(float4*)&out[o0 + SP] = r1[p];
            } else {
                float4 a0 = *(const float4*)&aux[o0];
                float4 a1 = *(const float4*)&aux[o0 + SP];
                float4 w0 = make_float4(a0.x/(1.f+expf(-r0[p].x)), a0.y/(1.f+expf(-r0[p].y)),
                                        a0.z/(1.f+expf(-r0[p].z)), a0.w/(1.f+expf(-r0[p].w)));
                float4 w1 = make_float4(a1.x/(1.f+expf(-r1[p].x)), a1.y/(1.f+expf(-r1[p].y)),
                                        a1.z/(1.f+expf(-r1[p].z)), a1.w/(1.f+expf(-r1[p].w)));
                *(float4*)&out[o0]      = w0;
                *(float4*)&out[o0 + SP] = w1;
            }
        }
    }
}

// ---------------- axial attention, head-contiguous layout ----------------
// qkv: [b][which][h][S][24]; osum: [b][h][S][24]. Rotation & pos_attn skipped
// (orthogonal R cancels in q.k; pa is constant along the softmax axis).
__global__ void __launch_bounds__(160) k_attn(const float* __restrict__ qkv, float* __restrict__ osum,
                                              int axis, int accum) {
    __shared__ __align__(16) float sq[3840], sk[3840], sv[3840];   // [h][l][24]
    int blk = blockIdx.x;
    int b = blk / 1600, r = blk % 1600, a1 = r/40, a2 = r%40;
    int base, lst;
    if (axis == 0)      { base = a1*ND + a2;     lst = HW; }
    else if (axis == 1) { base = a1*HW + a2;     lst = ND; }
    else                { base = a1*HW + a2*ND;  lst = 1;  }
    int t = threadIdx.x;

    const float* qb = qkv + (size_t)(b*3)*4*SP*24;
    for (int f=t; f<2880; f+=160) {
        int which = f/960, rr = f%960, h = rr/240, r2 = rr%240, l = r2/6, u = r2%6;
        float4 val = *(const float4*)&qb[((size_t)(which*4+h)*SP + base + (size_t)l*lst)*24 + u*4];
        float* dst = (which==0) ? sq : ((which==1) ? sk : sv);
        *(float4*)&dst[h*960 + l*24 + u*4] = val;
    }
    __syncthreads();

    int h = t/40, i = t%40;
    float4 q[6];
    #pragma unroll
    for (int u=0;u<6;u++) q[u] = *(const float4*)&sq[h*960 + i*24 + u*4];

    const float scale = 0.20412414523193154f;  // 1/sqrt(24)
    float S[40];
    float mx = -1e30f;
    #pragma unroll
    for (int j=0;j<40;j++) {
        const float4* kp = (const float4*)&sk[h*960 + j*24];
        float s = 0.f;
        #pragma unroll
        for (int u=0;u<6;u++) {
            float4 kv = kp[u];
            s += q[u].x*kv.x + q[u].y*kv.y + q[u].z*kv.z + q[u].w*kv.w;
        }
        s *= scale;
        S[j] = s;
        mx = fmaxf(mx, s);
    }
    float sum = 0.f;
    #pragma unroll
    for (int j=0;j<40;j++) { S[j] = expf(S[j]-mx); sum += S[j]; }
    float inv = 1.f/sum;

    float4 o[6];
    #pragma unroll
    for (int u=0;u<6;u++) o[u] = make_float4(0.f,0.f,0.f,0.f);
    #pragma unroll
    for (int j=0;j<40;j++) {
        float p = S[j]*inv;
        const float4* vp = (const float4*)&sv[h*960 + j*24];
        #pragma unroll
        for (int u=0;u<6;u++) {
            float4 vv = vp[u];
            o[u].x += p*vv.x; o[u].y += p*vv.y; o[u].z += p*vv.z; o[u].w += p*vv.w;
        }
    }
    size_t ob = ((size_t)(b*4+h)*SP + base + (size_t)i*lst)*24;
    #pragma unroll
    for (int u=0;u<6;u++) {
        float4 val = o[u];
        if (accum) {
            float4 old = *(const float4*)&osum[ob + u*4];
            val.x += old.x; val.y += old.y; val.z += old.z; val.w += old.w;
        }
        *(float4*)&osum[ob + u*4] = val;
    }
}

// ---------------- launch ----------------
extern "C" void kernel_launch(void* const* d_in, const int* in_sizes, int n_in,
                              void* d_out, int out_size) {
    const float* x      = (const float*)d_in[0];
    const float* pos    = (const float*)d_in[1];
    const float* qkv_w  = (const float*)d_in[2];
    const float* qkv_b  = (const float*)d_in[3];
    const float* lp1_w  = (const float*)d_in[4];
    const float* lp1_b  = (const float*)d_in[5];
    const float* lp2_w  = (const float*)d_in[6];
    const float* lp2_b  = (const float*)d_in[7];
    const float* mod1_w = (const float*)d_in[8];
    const float* mod1_b = (const float*)d_in[9];
    const float* mod2_w = (const float*)d_in[10];
    const float* mod2_b = (const float*)d_in[11];
    // d_in[12..16]: pa_w, pa_b, R6_d, R6_h, R6_w — mathematically unused
    const float* proj_w = (const float*)d_in[17];
    const float* proj_b = (const float*)d_in[18];
    float* out = (float*)d_out;

    float *buf1, *buf2, *xmod, *qkvp, *osum;
    cudaGetSymbolAddress((void**)&buf1, g_buf1);
    cudaGetSymbolAddress((void**)&buf2, g_buf2);
    cudaGetSymbolAddress((void**)&xmod, g_xmod);
    cudaGetSymbolAddress((void**)&qkvp, g_qkv);
    cudaGetSymbolAddress((void**)&osum, g_osum);

    k_wt<<<(NC*NC*27 + 255)/256, 256>>>(lp1_w);
    // local path: conv3 -> (IN+gelu fused into next gemm load)
    k_conv3<<<dim3(10,40,2), 256>>>(pos, lp1_b);
    k_stats<<<NB*NC, 256>>>(buf1);
    k_gemm<1,0><<<dim3(500,1,2), 256>>>(buf1, lp2_w, lp2_b, buf2, nullptr);   // local
    // mod path: conv1x1 -> (IN+gelu fused) -> conv1x1 + sigmoid*x fused
    k_gemm<0,0><<<dim3(500,1,2), 256>>>(buf2, mod1_w, mod1_b, buf1, nullptr);
    k_stats<<<NB*NC, 256>>>(buf1);
    k_gemm<1,1><<<dim3(500,1,2), 256>>>(buf1, mod2_w, mod2_b, xmod, x);       // x_mod
    // shared QKV projection, head-contiguous output layout
    k_gemm<0,2><<<dim3(500,3,2), 256>>>(xmod, qkv_w, qkv_b, qkvp, nullptr);
    // three axial attentions, accumulated into [b][h][S][24]
    k_attn<<<3200, 160>>>(qkvp, osum, 0, 0);
    k_attn<<<3200, 160>>>(qkvp, osum, 1, 1);
    k_attn<<<3200, 160>>>(qkvp, osum, 2, 1);
    // output projection (reads head layout)
    k_gemm<2,0><<<dim3(500,1,2), 256>>>(osum, proj_w, proj_b, out, nullptr);
}

// round 7
// speedup vs baseline: 1.3272x; 1.0638x over previous
#include <cuda_runtime.h>
#include <math.h>

#define NB 2
#define NC 96
#define ND 40
#define HW 1600
#define SP 64000   // 40*40*40

typedef unsigned long long ull;

// ---------------- scratch (no allocs allowed) ----------------
__device__ float g_buf1[NB*NC*SP];
__device__ float g_buf2[NB*NC*SP];
__device__ float g_xmod[NB*NC*SP];
__device__ float g_qkv [NB*3*4*SP*24];    // [b][which][head][S][24]
__device__ float g_osum[3*NB*4*SP*24];    // [axis][b][head][S][24]
__device__ float g_stats[NB*NC*2];
__device__ float g_wt[NC*NC*27];          // conv3 weights as [ci][tap][co]

#define OSLAB ((size_t)NB*4*SP*24)

// ---------------- packed fp32x2 helpers ----------------
__device__ __forceinline__ void ffma2(ull &acc, ull w, ull x) {
    asm("fma.rn.f32x2 %0, %1, %2, %0;" : "+l"(acc) : "l"(w), "l"(x));
}
__device__ __forceinline__ ull bcast2(float x) {
    ull r;
    asm("mov.b64 %0, {%1, %1};" : "=l"(r) : "f"(x));
    return r;
}
__device__ __forceinline__ float2 unpack2(ull v) {
    float2 r;
    asm("mov.b64 {%0, %1}, %2;" : "=f"(r.x), "=f"(r.y) : "l"(v));
    return r;
}

// ---------------- weight transpose for conv3 ----------------
__global__ void k_wt(const float* __restrict__ w) {
    int idx = blockIdx.x*256 + threadIdx.x;
    if (idx >= NC*NC*27) return;
    int co  = idx % NC;
    int tap = (idx/NC) % 27;
    int ci  = idx/(NC*27);
    g_wt[idx] = w[(co*NC + ci)*27 + tap];
}

// ---------------- conv 3x3x3 circular (pos_emb -> g_buf1) ----------------
// block: (b, d, 4 h-rows). out tile: 96 co x 4 h x 40 w. 256 thr:
// 8 co-groups (12 co = 6 f32x2 pairs) x 32 s-groups (5 w each).
// Inner loop: xb[7] hoisted per row; weights via LDS.128 pairs.
__global__ void __launch_bounds__(256) k_conv3(const float* __restrict__ x, const float* __restrict__ bias) {
    __shared__ __align__(16) float s_in[3*756];     // [ci3][dd3][hh6][ww42]
    __shared__ __align__(16) float s_w [3*2592];    // [ci3][tap27][co96]
    int b = blockIdx.z, d = blockIdx.y, h0 = blockIdx.x*4;
    int t = threadIdx.x;
    int sg = t & 31, cg = t >> 5;
    int s0 = sg*5, hp = s0/40, w0 = s0%40;
    int co0 = cg*12;

    ull acc[6][5];
    #pragma unroll
    for (int p=0;p<6;p++)
        #pragma unroll
        for (int j=0;j<5;j++) acc[p][j] = 0ull;

    for (int ci0=0; ci0<NC; ci0+=3) {
        __syncthreads();
        for (int idx=t; idx<3*756; idx+=256) {
            int ci = idx/756, r = idx%756;
            int dd = r/252, r2 = r%252, hh = r2/42, ww = r2%42;
            int gd = d+dd-1;  if (gd<0) gd+=ND; else if (gd>=ND) gd-=ND;
            int gh = h0+hh-1; if (gh<0) gh+=ND; else if (gh>=ND) gh-=ND;
            int gw = ww-1;    if (gw<0) gw+=ND; else if (gw>=ND) gw-=ND;
            s_in[idx] = x[(size_t)(b*NC+ci0+ci)*SP + gd*HW + gh*ND + gw];
        }
        for (int idx=t; idx<3*2592; idx+=256)
            s_w[idx] = g_wt[ci0*2592 + idx];
        __syncthreads();

        #pragma unroll 1
        for (int ci=0; ci<3; ci++) {
            #pragma unroll
            for (int kd=0; kd<3; kd++) {
                #pragma unroll
                for (int kh=0; kh<3; kh++) {
                    const float* xin = &s_in[ci*756 + kd*252 + (hp+kh)*42 + w0];
                    ull xb[7];
                    #pragma unroll
                    for (int m=0;m<7;m++) xb[m] = bcast2(xin[m]);
                    #pragma unroll
                    for (int kw=0; kw<3; kw++) {
                        const float* wp = &s_w[(ci*27 + kd*9 + kh*3 + kw)*NC + co0];
                        ulonglong2 w01 = *(const ulonglong2*)(wp);
                        ulonglong2 w23 = *(const ulonglong2*)(wp+4);
                        ulonglong2 w45 = *(const ulonglong2*)(wp+8);
                        #pragma unroll
                        for (int j=0;j<5;j++) {
                            ull xv = xb[kw+j];
                            ffma2(acc[0][j], w01.x, xv);
                            ffma2(acc[1][j], w01.y, xv);
                            ffma2(acc[2][j], w23.x, xv);
                            ffma2(acc[3][j], w23.y, xv);
                            ffma2(acc[4][j], w45.x, xv);
                            ffma2(acc[5][j], w45.y, xv);
                        }
                    }
                }
            }
        }
    }
    int h = h0 + hp;
    #pragma unroll
    for (int p=0;p<6;p++) {
        int c = co0 + 2*p;
        float b0 = bias[c], b1 = bias[c+1];
        #pragma unroll
        for (int j=0;j<5;j++) {
            float2 v = unpack2(acc[p][j]);
            size_t off = (size_t)(b*NC+c)*SP + d*HW + h*ND + (w0+j);
            g_buf1[off]      = v.x + b0;
            g_buf1[off + SP] = v.y + b1;
        }
    }
}

// ---------------- instance-norm stats per (b,c) ----------------
__global__ void __launch_bounds__(256) k_stats(const float* __restrict__ x) {
    __shared__ double ss[256], ss2[256];
    int bc = blockIdx.x, t = threadIdx.x;
    const float* p = x + (size_t)bc*SP;
    double s=0.0, s2=0.0;
    for (int i=t; i<SP; i+=256) { double v = p[i]; s += v; s2 += v*v; }
    ss[t]=s; ss2[t]=s2; __syncthreads();
    for (int o=128;o>0;o>>=1){ if(t<o){ss[t]+=ss[t+o]; ss2[t]+=ss2[t+o];} __syncthreads(); }
    if (t==0) {
        double mu  = ss[0]/(double)SP;
        double var = ss2[0]/(double)SP - mu*mu;
        g_stats[bc*2]   = (float)mu;
        g_stats[bc*2+1] = (float)(1.0/sqrt(var + 1e-5));
    }
}

// ---------------- fused conv1x1 GEMM, full-K resident in smem ----------------
// IN_MODE:  0 = plain [b][c][S]   1 = instance-norm + exact gelu on load
//           2 = sum of 3 attention slabs, head layout [axis][b][h][S][24]
// OUT_MODE: 0 = plain [b][c][S]   1 = sigmoid(res)*aux (mod gate fused with x)
//           2 = QKV head layout [b][which][h][S][24], which = blockIdx.y
// dynamic smem: s_x[96*128] + s_w[96*100] = 87552 bytes
template<int IN_MODE, int OUT_MODE>
__global__ void __launch_bounds__(256) k_gemm(const float* __restrict__ in, const float* __restrict__ W,
                                              const float* __restrict__ bias, float* __restrict__ out,
                                              const float* __restrict__ aux) {
    extern __shared__ __align__(16) float s_mem[];
    float* s_x = s_mem;            // [ci=96][s=128]
    float* s_w = s_mem + 12288;    // [ci=96][co pad 100]
    int b = blockIdx.z, s0 = blockIdx.x*128, grp = blockIdx.y;
    int co0 = grp*96;
    int t = threadIdx.x, tx = t & 31, ty = t >> 5;

    // ---- load X tile ----
    if constexpr (IN_MODE == 2) {
        for (int f=t; f<3072; f+=256) {
            int h = f/768, rem = f%768, s = rem/6, u = rem%6;
            size_t gi = ((size_t)(b*4+h)*SP + s0 + s)*24 + u*4;
            float4 a = *(const float4*)&in[gi];
            float4 c = *(const float4*)&in[gi + OSLAB];
            float4 e = *(const float4*)&in[gi + 2*OSLAB];
            int cbase = (h*24 + u*4)*128 + s;
            s_x[cbase      ] = a.x + c.x + e.x;
            s_x[cbase + 128] = a.y + c.y + e.y;
            s_x[cbase + 256] = a.z + c.z + e.z;
            s_x[cbase + 384] = a.w + c.w + e.w;
        }
    } else {
        for (int idx=t; idx<3072; idx+=256) {
            int ci = idx>>5, s4 = (idx&31)*4;
            float4 v = *(const float4*)&in[(size_t)(b*NC+ci)*SP + s0 + s4];
            if constexpr (IN_MODE == 1) {
                int bc = b*NC+ci;
                float mu = g_stats[bc*2], rs = g_stats[bc*2+1];
                v.x = (v.x-mu)*rs; v.x = 0.5f*v.x*(1.0f+erff(v.x*0.70710678118654752f));
                v.y = (v.y-mu)*rs; v.y = 0.5f*v.y*(1.0f+erff(v.y*0.70710678118654752f));
                v.z = (v.z-mu)*rs; v.z = 0.5f*v.z*(1.0f+erff(v.z*0.70710678118654752f));
                v.w = (v.w-mu)*rs; v.w = 0.5f*v.w*(1.0f+erff(v.w*0.70710678118654752f));
            }
            *(float4*)&s_x[ci*128 + s4] = v;
        }
    }
    // ---- load W tile (96 co x 96 ci, stored [ci][co]) ----
    for (int idx=t; idx<2304; idx+=256) {
        int co = idx/24, ci4 = (idx%24)*4;
        float4 w = *(const float4*)&W[(size_t)(co0+co)*NC + ci4];
        s_w[(ci4+0)*100 + co] = w.x;
        s_w[(ci4+1)*100 + co] = w.y;
        s_w[(ci4+2)*100 + co] = w.z;
        s_w[(ci4+3)*100 + co] = w.w;
    }
    __syncthreads();

    ull acc[6][4];
    #pragma unroll
    for (int p=0;p<6;p++)
        #pragma unroll
        for (int j=0;j<4;j++) acc[p][j] = 0ull;

    const float* xrow = s_x + tx*4;
    const float* wrow = s_w + ty*12;
    #pragma unroll 8
    for (int ci=0; ci<96; ci++) {
        float4 xv = *(const float4*)(xrow + ci*128);
        ull xb[4] = { bcast2(xv.x), bcast2(xv.y), bcast2(xv.z), bcast2(xv.w) };
        const float* wp = wrow + ci*100;
        ulonglong2 w01 = *(const ulonglong2*)(wp);
        ulonglong2 w23 = *(const ulonglong2*)(wp+4);
        ulonglong2 w45 = *(const ulonglong2*)(wp+8);
        #pragma unroll
        for (int j=0;j<4;j++) {
            ffma2(acc[0][j], w01.x, xb[j]);
            ffma2(acc[1][j], w01.y, xb[j]);
            ffma2(acc[2][j], w23.x, xb[j]);
            ffma2(acc[3][j], w23.y, xb[j]);
            ffma2(acc[4][j], w45.x, xb[j]);
            ffma2(acc[5][j], w45.y, xb[j]);
        }
    }

    // epilogue: unpack to float4 rows (s-major) with bias
    float4 r0[6], r1[6];
    #pragma unroll
    for (int p=0;p<6;p++) {
        int c = ty*12 + 2*p;
        float b0 = bias[co0 + c], b1 = bias[co0 + c + 1];
        float2 v[4];
        #pragma unroll
        for (int j=0;j<4;j++) { v[j] = unpack2(acc[p][j]); v[j].x += b0; v[j].y += b1; }
        r0[p] = make_float4(v[0].x, v[1].x, v[2].x, v[3].x);
        r1[p] = make_float4(v[0].y, v[1].y, v[2].y, v[3].y);
    }

    if constexpr (OUT_MODE == 2) {
        __syncthreads();                  // s_x/s_w dead, reuse as s_out[96 co][128 s]
        float* s_out = s_mem;
        #pragma unroll
        for (int p=0;p<6;p++) {
            int c = ty*12 + 2*p;
            *(float4*)&s_out[c*128 + tx*4]     = r0[p];
            *(float4*)&s_out[(c+1)*128 + tx*4] = r1[p];
        }
        __syncthreads();
        float* ob = out + ((size_t)(b*3 + grp)*4)*SP*24;
        for (int f=t; f<3072; f+=256) {
            int h = f/768, rem = f%768, s = rem/6, u = rem%6;
            float4 r;
            r.x = s_out[(h*24+u*4+0)*128 + s];
            r.y = s_out[(h*24+u*4+1)*128 + s];
            r.z = s_out[(h*24+u*4+2)*128 + s];
            r.w = s_out[(h*24+u*4+3)*128 + s];
            *(float4*)&ob[((size_t)h*SP + s0 + s)*24 + u*4] = r;
        }
    } else {
        #pragma unroll
        for (int p=0;p<6;p++) {
            int c = ty*12 + 2*p;
            size_t o0 = (size_t)(b*NC + c)*SP + s0 + tx*4;
            if constexpr (OUT_MODE == 0) {
                *(float4*)&out[o0]      = r0[p];
                *(float4*)&out[o0 + SP] = r1[p];
            } else {
                float4 a0 = *(const float4*)&aux[o0];
                float4 a1 = *(const float4*)&aux[o0 + SP];
                float4 w0 = make_float4(a0.x/(1.f+expf(-r0[p].x)), a0.y/(1.f+expf(-r0[p].y)),
                                        a0.z/(1.f+expf(-r0[p].z)), a0.w/(1.f+expf(-r0[p].w)));
                float4 w1 = make_float4(a1.x/(1.f+expf(-r1[p].x)), a1.y/(1.f+expf(-r1[p].y)),
                                        a1.z/(1.f+expf(-r1[p].z)), a1.w/(1.f+expf(-r1[p].w)));
                *(float4*)&out[o0]      = w0;
                *(float4*)&out[o0 + SP] = w1;
            }
        }
    }
}

// ---------------- axial attention, all 3 axes in one launch ----------------
// qkv: [b][which][h][S][24]; osum slab per axis: [axis][b][h][S][24].
// Rotation & pos_attn skipped (orthogonal R cancels in q.k; pa constant per row).
__global__ void __launch_bounds__(160) k_attn(const float* __restrict__ qkv, float* __restrict__ osum) {
    __shared__ __align__(16) float sq[3840], sk[3840], sv[3840];   // [h][l][24]
    int axis = blockIdx.y;
    int blk = blockIdx.x;
    int b = blk / 1600, r = blk % 1600, a1 = r/40, a2 = r%40;
    int base, lst;
    if (axis == 0)      { base = a1*ND + a2;     lst = HW; }
    else if (axis == 1) { base = a1*HW + a2;     lst = ND; }
    else                { base = a1*HW + a2*ND;  lst = 1;  }
    int t = threadIdx.x;

    const float* qb = qkv + (size_t)(b*3)*4*SP*24;
    for (int f=t; f<2880; f+=160) {
        int which = f/960, rr = f%960, h = rr/240, r2 = rr%240, l = r2/6, u = r2%6;
        float4 val = *(const float4*)&qb[((size_t)(which*4+h)*SP + base + (size_t)l*lst)*24 + u*4];
        float* dst = (which==0) ? sq : ((which==1) ? sk : sv);
        *(float4*)&dst[h*960 + l*24 + u*4] = val;
    }
    __syncthreads();

    int h = t/40, i = t%40;
    float4 q[6];
    #pragma unroll
    for (int u=0;u<6;u++) q[u] = *(const float4*)&sq[h*960 + i*24 + u*4];

    const float scale = 0.20412414523193154f;  // 1/sqrt(24)
    float S[40];
    float mx = -1e30f;
    #pragma unroll
    for (int j=0;j<40;j++) {
        const float4* kp = (const float4*)&sk[h*960 + j*24];
        float s = 0.f;
        #pragma unroll
        for (int u=0;u<6;u++) {
            float4 kv = kp[u];
            s += q[u].x*kv.x + q[u].y*kv.y + q[u].z*kv.z + q[u].w*kv.w;
        }
        s *= scale;
        S[j] = s;
        mx = fmaxf(mx, s);
    }
    float sum = 0.f;
    #pragma unroll
    for (int j=0;j<40;j++) { S[j] = expf(S[j]-mx); sum += S[j]; }
    float inv = 1.f/sum;

    float4 o[6];
    #pragma unroll
    for (int u=0;u<6;u++) o[u] = make_float4(0.f,0.f,0.f,0.f);
    #pragma unroll
    for (int j=0;j<40;j++) {
        float p = S[j]*inv;
        const float4* vp = (const float4*)&sv[h*960 + j*24];
        #pragma unroll
        for (int u=0;u<6;u++) {
            float4 vv = vp[u];
            o[u].x += p*vv.x; o[u].y += p*vv.y; o[u].z += p*vv.z; o[u].w += p*vv.w;
        }
    }
    size_t ob = (size_t)axis*OSLAB + ((size_t)(b*4+h)*SP + base + (size_t)i*lst)*24;
    #pragma unroll
    for (int u=0;u<6;u++)
        *(float4*)&osum[ob + u*4] = o[u];
}

// ---------------- launch ----------------
extern "C" void kernel_launch(void* const* d_in, const int* in_sizes, int n_in,
                              void* d_out, int out_size) {
    const float* x      = (const float*)d_in[0];
    const float* pos    = (const float*)d_in[1];
    const float* qkv_w  = (const float*)d_in[2];
    const float* qkv_b  = (const float*)d_in[3];
    const float* lp1_w  = (const float*)d_in[4];
    const float* lp1_b  = (const float*)d_in[5];
    const float* lp2_w  = (const float*)d_in[6];
    const float* lp2_b  = (const float*)d_in[7];
    const float* mod1_w = (const float*)d_in[8];
    const float* mod1_b = (const float*)d_in[9];
    const float* mod2_w = (const float*)d_in[10];
    const float* mod2_b = (const float*)d_in[11];
    // d_in[12..16]: pa_w, pa_b, R6_d, R6_h, R6_w — mathematically unused
    const float* proj_w = (const float*)d_in[17];
    const float* proj_b = (const float*)d_in[18];
    float* out = (float*)d_out;

    float *buf1, *buf2, *xmod, *qkvp, *osum;
    cudaGetSymbolAddress((void**)&buf1, g_buf1);
    cudaGetSymbolAddress((void**)&buf2, g_buf2);
    cudaGetSymbolAddress((void**)&xmod, g_xmod);
    cudaGetSymbolAddress((void**)&qkvp, g_qkv);
    cudaGetSymbolAddress((void**)&osum, g_osum);

    const int GS = (12288 + 9600) * 4;   // 87552 B dynamic smem
    cudaFuncSetAttribute(k_gemm<1,0>, cudaFuncAttributeMaxDynamicSharedMemorySize, GS);
    cudaFuncSetAttribute(k_gemm<0,0>, cudaFuncAttributeMaxDynamicSharedMemorySize, GS);
    cudaFuncSetAttribute(k_gemm<1,1>, cudaFuncAttributeMaxDynamicSharedMemorySize, GS);
    cudaFuncSetAttribute(k_gemm<0,2>, cudaFuncAttributeMaxDynamicSharedMemorySize, GS);
    cudaFuncSetAttribute(k_gemm<2,0>, cudaFuncAttributeMaxDynamicSharedMemorySize, GS);

    k_wt<<<(NC*NC*27 + 255)/256, 256>>>(lp1_w);
    // local path: conv3 -> (IN+gelu fused into next gemm load)
    k_conv3<<<dim3(10,40,2), 256>>>(pos, lp1_b);
    k_stats<<<NB*NC, 256>>>(buf1);
    k_gemm<1,0><<<dim3(500,1,2), 256, GS>>>(buf1, lp2_w, lp2_b, buf2, nullptr);   // local
    // mod path: conv1x1 -> (IN+gelu fused) -> conv1x1 + sigmoid*x fused
    k_gemm<0,0><<<dim3(500,1,2), 256, GS>>>(buf2, mod1_w, mod1_b, buf1, nullptr);
    k_stats<<<NB*NC, 256>>>(buf1);
    k_gemm<1,1><<<dim3(500,1,2), 256, GS>>>(buf1, mod2_w, mod2_b, xmod, x);       // x_mod
    // shared QKV projection, head-contiguous output layout
    k_gemm<0,2><<<dim3(500,3,2), 256, GS>>>(xmod, qkv_w, qkv_b, qkvp, nullptr);
    // three axial attentions in one launch, separate slabs
    k_attn<<<dim3(3200,3), 160>>>(qkvp, osum);
    // output projection (reads + sums the 3 slabs)
    k_gemm<2,0><<<dim3(500,1,2), 256, GS>>>(osum, proj_w, proj_b, out, nullptr);
}

// round 10
// speedup vs baseline: 1.4677x; 1.1058x over previous
#include <cuda_runtime.h>
#include <math.h>
#include <cstdint>

#define NB 2
#define NC 96
#define ND 40
#define HW 1600
#define SP 64000   // 40*40*40

typedef unsigned long long ull;

// ---------------- scratch (no allocs allowed) ----------------
__device__ float g_buf1[NB*NC*SP];
__device__ float g_buf2[NB*NC*SP];
__device__ float g_xmod[NB*NC*SP];
__device__ float g_qkv [NB*3*4*SP*24];    // [b][which][head][S][24]
__device__ float g_osum[3*NB*4*SP*24];    // [axis][b][head][S][24]
__device__ float g_stats[NB*NC*2];
__device__ float g_xt[NB*SP*NC];          // pos_emb transposed: [b][s][ci]
__device__ float g_wc3[2*27*NC*NC];       // conv3 weights: [prec][tap][ci][co]

#define OSLAB ((size_t)NB*4*SP*24)

// ---------------- packed fp32x2 helpers ----------------
__device__ __forceinline__ void ffma2(ull &acc, ull w, ull x) {
    asm("fma.rn.f32x2 %0, %1, %2, %0;" : "+l"(acc) : "l"(w), "l"(x));
}
__device__ __forceinline__ ull bcast2(float x) {
    ull r;
    asm("mov.b64 %0, {%1, %1};" : "=l"(r) : "f"(x));
    return r;
}
__device__ __forceinline__ float2 unpack2(ull v) {
    float2 r;
    asm("mov.b64 {%0, %1}, %2;" : "=f"(r.x), "=f"(r.y) : "l"(v));
    return r;
}

// ---------------- tf32 helpers ----------------
__device__ __forceinline__ float tf32r(float x) {
    uint32_t u;
    asm("cvt.rna.tf32.f32 %0, %1;" : "=r"(u) : "f"(x));
    return __uint_as_float(u);
}
// D(16x8,f32) += A(16x8,tf32,row) * B(8x8,tf32,col)
__device__ __forceinline__ void mma8(float* d, const uint32_t* a, uint32_t b0, uint32_t b1) {
    asm volatile("mma.sync.aligned.m16n8k8.row.col.f32.tf32.tf32.f32 "
        "{%0,%1,%2,%3}, {%4,%5,%6,%7}, {%8,%9}, {%0,%1,%2,%3};"
        : "+f"(d[0]), "+f"(d[1]), "+f"(d[2]), "+f"(d[3])
        : "r"(a[0]), "r"(a[1]), "r"(a[2]), "r"(a[3]), "r"(b0), "r"(b1));
}

// ---------------- prep: transpose pos_emb [b][c][s] -> [b][s][c] ----------------
__global__ void __launch_bounds__(256) k_xt(const float* __restrict__ x) {
    __shared__ float tile[32][65];
    int sblk = blockIdx.x, cb = blockIdx.y, b = blockIdx.z;
    int t = threadIdx.x;
    for (int i=t; i<2048; i+=256) {
        int c = i>>6, s = i&63;
        tile[c][s] = x[(size_t)(b*NC + cb*32 + c)*SP + sblk*64 + s];
    }
    __syncthreads();
    for (int i=t; i<2048; i+=256) {
        int s = i>>5, c = i&31;
        g_xt[((size_t)b*SP + sblk*64 + s)*NC + cb*32 + c] = tile[c][s];
    }
}

// ---------------- prep: conv3 weights -> tf32 hi/lo, [prec][tap][ci][co] ----------------
__global__ void k_wc3prep(const float* __restrict__ w) {
    int idx = blockIdx.x*256 + threadIdx.x;
    if (idx >= 2*27*NC*NC) return;
    int co  = idx % NC;
    int ci  = (idx/NC) % NC;
    int tap = (idx/(NC*NC)) % 27;
    int p   = idx/(NC*NC*27);
    float v = w[((size_t)co*NC + ci)*27 + tap];
    float hi = tf32r(v);
    g_wc3[idx] = (p==0) ? hi : tf32r(v - hi);
}

// ---------------- conv 3x3x3 circular via mma.sync tf32 (3xTF32) ----------------
// Block: 128 consecutive (b,s) rows x 96 co. 81 stages = 27 taps x 3 ci-chunks(32).
// smem floats: A_hi[128][36] @0, A_lo @4608, W_hi[32][104] @9216, W_lo @12544. (63488 B)
#define SA_LO 4608
#define SW_HI 9216
#define SW_LO 12544
#define CONV_SMEM_F 15872

__global__ void __launch_bounds__(256) k_conv3_mma(const float* __restrict__ bias) {
    extern __shared__ __align__(16) float s_f[];
    int t = threadIdx.x;
    int wid = t>>5, lid = t&31;
    int g8 = lid>>2, t4 = lid&3;
    int wm = wid>>1, wn = wid&1;
    int gs0 = blockIdx.x * 128;
    int b = gs0 / SP, sbase = gs0 % SP;

    float d[2][6][4];
    #pragma unroll
    for (int s=0;s<2;s++)
        #pragma unroll
        for (int n=0;n<6;n++)
            #pragma unroll
            for (int k=0;k<4;k++) d[s][n][k] = 0.f;

    for (int tap=0; tap<27; tap++) {
        int kd = tap/9, kh = (tap/3)%3, kw = tap%3;
        for (int cc=0; cc<3; cc++) {
            int ci0 = cc*32;
            // ---- stage A: 128 rows x 32 ci, hi/lo split ----
            #pragma unroll
            for (int it=0; it<4; it++) {
                int idx = t + it*256;
                int row = idx >> 3, ci4 = idx & 7;
                int s = sbase + row;
                int dz = s/1600; int r = s - dz*1600; int hz = r/40; int wz = r - hz*40;
                int dd = dz + kd - 1; if (dd<0) dd+=ND; else if (dd>=ND) dd-=ND;
                int hh = hz + kh - 1; if (hh<0) hh+=ND; else if (hh>=ND) hh-=ND;
                int ww = wz + kw - 1; if (ww<0) ww+=ND; else if (ww>=ND) ww-=ND;
                float4 v = *(const float4*)&g_xt[((size_t)b*SP + dd*HW + hh*ND + ww)*NC + ci0 + ci4*4];
                float4 hi, lo;
                hi.x = tf32r(v.x); hi.y = tf32r(v.y); hi.z = tf32r(v.z); hi.w = tf32r(v.w);
                lo.x = tf32r(v.x-hi.x); lo.y = tf32r(v.y-hi.y); lo.z = tf32r(v.z-hi.z); lo.w = tf32r(v.w-hi.w);
                *(float4*)&s_f[row*36 + ci4*4]         = hi;
                *(float4*)&s_f[SA_LO + row*36 + ci4*4] = lo;
            }
            // ---- stage W: hi/lo [32 ci][96 co] -> [ci][co pad 104] ----
            #pragma unroll
            for (int it=0; it<6; it++) {
                int idx = t + it*256;
                int p = idx/768, r = idx - p*768;
                int ci = r/24, co4 = r - ci*24;
                float4 v = *(const float4*)&g_wc3[(((size_t)p*27+tap)*NC + ci0+ci)*NC + co4*4];
                *(float4*)&s_f[SW_HI + p*3328 + ci*104 + co4*4] = v;
            }
            __syncthreads();

            // ---- compute: 4 k-steps x 6 n-tiles x 2 m-subtiles x 3 mma ----
            #pragma unroll
            for (int k0=0; k0<32; k0+=8) {
                uint32_t ah[2][4], al[2][4];
                #pragma unroll
                for (int sub=0; sub<2; sub++) {
                    const float* pa = s_f + (wm*32 + sub*16 + g8)*36 + k0 + t4;
                    ah[sub][0] = __float_as_uint(pa[0]);
                    ah[sub][1] = __float_as_uint(pa[8*36]);
                    ah[sub][2] = __float_as_uint(pa[4]);
                    ah[sub][3] = __float_as_uint(pa[8*36+4]);
                    const float* pl = pa + SA_LO;
                    al[sub][0] = __float_as_uint(pl[0]);
                    al[sub][1] = __float_as_uint(pl[8*36]);
                    al[sub][2] = __float_as_uint(pl[4]);
                    al[sub][3] = __float_as_uint(pl[8*36+4]);
                }
                #pragma unroll
                for (int nt=0; nt<6; nt++) {
                    const float* pb = s_f + SW_HI + (k0+t4)*104 + wn*48 + nt*8 + g8;
                    uint32_t bh0 = __float_as_uint(pb[0]);
                    uint32_t bh1 = __float_as_uint(pb[4*104]);
                    uint32_t bl0 = __float_as_uint(pb[3328]);
                    uint32_t bl1 = __float_as_uint(pb[3328 + 4*104]);
                    #pragma unroll
                    for (int sub=0; sub<2; sub++) {
                        mma8(d[sub][nt], ah[sub], bh0, bh1);
                        mma8(d[sub][nt], al[sub], bh0, bh1);
                        mma8(d[sub][nt], ah[sub], bl0, bl1);
                    }
                }
            }
            __syncthreads();
        }
    }

    // ---- epilogue: d frags -> s_out[96 co][132 pad] -> coalesced gmem ----
    float* s_out = s_f;
    #pragma unroll
    for (int sub=0; sub<2; sub++) {
        int row0 = wm*32 + sub*16 + g8;
        #pragma unroll
        for (int nt=0; nt<6; nt++) {
            int c0 = wn*48 + nt*8 + t4*2;
            s_out[(c0  )*132 + row0]     = d[sub][nt][0];
            s_out[(c0+1)*132 + row0]     = d[sub][nt][1];
            s_out[(c0  )*132 + row0 + 8] = d[sub][nt][2];
            s_out[(c0+1)*132 + row0 + 8] = d[sub][nt][3];
        }
    }
    __syncthreads();
    for (int i=t; i<3072; i+=256) {
        int co = i>>5, s4 = (i&31)*4;
        float4 v = *(const float4*)&s_out[co*132 + s4];
        float bb = bias[co];
        v.x += bb; v.y += bb; v.z += bb; v.w += bb;
        *(float4*)&g_buf1[(size_t)(b*NC+co)*SP + sbase + s4] = v;
    }
}

// ---------------- instance-norm stats per (b,c) ----------------
__global__ void __launch_bounds__(256) k_stats(const float* __restrict__ x) {
    __shared__ double ss[256], ss2[256];
    int bc = blockIdx.x, t = threadIdx.x;
    const float* p = x + (size_t)bc*SP;
    double s=0.0, s2=0.0;
    for (int i=t; i<SP; i+=256) { double v = p[i]; s += v; s2 += v*v; }
    ss[t]=s; ss2[t]=s2; __syncthreads();
    for (int o=128;o>0;o>>=1){ if(t<o){ss[t]+=ss[t+o]; ss2[t]+=ss2[t+o];} __syncthreads(); }
    if (t==0) {
        double mu  = ss[0]/(double)SP;
        double var = ss2[0]/(double)SP - mu*mu;
        g_stats[bc*2]   = (float)mu;
        g_stats[bc*2+1] = (float)(1.0/sqrt(var + 1e-5));
    }
}

// ---------------- fused conv1x1 GEMM, full-K resident in smem ----------------
// IN_MODE:  0 plain [b][c][S]   1 IN+gelu on load   2 sum of 3 attn slabs [axis][b][h][S][24]
// OUT_MODE: 0 plain [b][c][S]   1 sigmoid(res)*aux  2 QKV head layout, which = blockIdx.y
template<int IN_MODE, int OUT_MODE>
__global__ void __launch_bounds__(256) k_gemm(const float* __restrict__ in, const float* __restrict__ W,
                                              const float* __restrict__ bias, float* __restrict__ out,
                                              const float* __restrict__ aux) {
    extern __shared__ __align__(16) float s_mem[];
    float* s_x = s_mem;            // [ci=96][s=128]
    float* s_w = s_mem + 12288;    // [ci=96][co pad 100]
    int b = blockIdx.z, s0 = blockIdx.x*128, grp = blockIdx.y;
    int co0 = grp*96;
    int t = threadIdx.x, tx = t & 31, ty = t >> 5;

    if constexpr (IN_MODE == 2) {
        for (int f=t; f<3072; f+=256) {
            int h = f/768, rem = f%768, s = rem/6, u = rem%6;
            size_t gi = ((size_t)(b*4+h)*SP + s0 + s)*24 + u*4;
            float4 a = *(const float4*)&in[gi];
            float4 c = *(const float4*)&in[gi + OSLAB];
            float4 e = *(const float4*)&in[gi + 2*OSLAB];
            int cbase = (h*24 + u*4)*128 + s;
            s_x[cbase      ] = a.x + c.x + e.x;
            s_x[cbase + 128] = a.y + c.y + e.y;
            s_x[cbase + 256] = a.z + c.z + e.z;
            s_x[cbase + 384] = a.w + c.w + e.w;
        }
    } else {
        for (int idx=t; idx<3072; idx+=256) {
            int ci = idx>>5, s4 = (idx&31)*4;
            float4 v = *(const float4*)&in[(size_t)(b*NC+ci)*SP + s0 + s4];
            if constexpr (IN_MODE == 1) {
                int bc = b*NC+ci;
                float mu = g_stats[bc*2], rs = g_stats[bc*2+1];
                v.x = (v.x-mu)*rs; v.x = 0.5f*v.x*(1.0f+erff(v.x*0.70710678118654752f));
                v.y = (v.y-mu)*rs; v.y = 0.5f*v.y*(1.0f+erff(v.y*0.70710678118654752f));
                v.z = (v.z-mu)*rs; v.z = 0.5f*v.z*(1.0f+erff(v.z*0.70710678118654752f));
                v.w = (v.w-mu)*rs; v.w = 0.5f*v.w*(1.0f+erff(v.w*0.70710678118654752f));
            }
            *(float4*)&s_x[ci*128 + s4] = v;
        }
    }
    for (int idx=t; idx<2304; idx+=256) {
        int co = idx/24, ci4 = (idx%24)*4;
        float4 w = *(const float4*)&W[(size_t)(co0+co)*NC + ci4];
        s_w[(ci4+0)*100 + co] = w.x;
        s_w[(ci4+1)*100 + co] = w.y;
        s_w[(ci4+2)*100 + co] = w.z;
        s_w[(ci4+3)*100 + co] = w.w;
    }
    __syncthreads();

    ull acc[6][4];
    #pragma unroll
    for (int p=0;p<6;p++)
        #pragma unroll
        for (int j=0;j<4;j++) acc[p][j] = 0ull;

    const float* xrow = s_x + tx*4;
    const float* wrow = s_w + ty*12;
    #pragma unroll 8
    for (int ci=0; ci<96; ci++) {
        float4 xv = *(const float4*)(xrow + ci*128);
        ull xb[4] = { bcast2(xv.x), bcast2(xv.y), bcast2(xv.z), bcast2(xv.w) };
        const float* wp = wrow + ci*100;
        ulonglong2 w01 = *(const ulonglong2*)(wp);
        ulonglong2 w23 = *(const ulonglong2*)(wp+4);
        ulonglong2 w45 = *(const ulonglong2*)(wp+8);
        #pragma unroll
        for (int j=0;j<4;j++) {
            ffma2(acc[0][j], w01.x, xb[j]);
            ffma2(acc[1][j], w01.y, xb[j]);
            ffma2(acc[2][j], w23.x, xb[j]);
            ffma2(acc[3][j], w23.y, xb[j]);
            ffma2(acc[4][j], w45.x, xb[j]);
            ffma2(acc[5][j], w45.y, xb[j]);
        }
    }

    float4 r0[6], r1[6];
    #pragma unroll
    for (int p=0;p<6;p++) {
        int c = ty*12 + 2*p;
        float b0 = bias[co0 + c], b1 = bias[co0 + c + 1];
        float2 v[4];
        #pragma unroll
        for (int j=0;j<4;j++) { v[j] = unpack2(acc[p][j]); v[j].x += b0; v[j].y += b1; }
        r0[p] = make_float4(v[0].x, v[1].x, v[2].x, v[3].x);
        r1[p] = make_float4(v[0].y, v[1].y, v[2].y, v[3].y);
    }

    if constexpr (OUT_MODE == 2) {
        __syncthreads();
        float* s_out = s_mem;
        #pragma unroll
        for (int p=0;p<6;p++) {
            int c = ty*12 + 2*p;
            *(float4*)&s_out[c*128 + tx*4]     = r0[p];
            *(float4*)&s_out[(c+1)*128 + tx*4] = r1[p];
        }
        __syncthreads();
        float* ob = out + ((size_t)(b*3 + grp)*4)*SP*24;
        for (int f=t; f<3072; f+=256) {
            int h = f/768, rem = f%768, s = rem/6, u = rem%6;
            float4 r;
            r.x = s_out[(h*24+u*4+0)*128 + s];
            r.y = s_out[(h*24+u*4+1)*128 + s];
            r.z = s_out[(h*24+u*4+2)*128 + s];
            r.w = s_out[(h*24+u*4+3)*128 + s];
            *(float4*)&ob[((size_t)h*SP + s0 + s)*24 + u*4] = r;
        }
    } else {
        #pragma unroll
        for (int p=0;p<6;p++) {
            int c = ty*12 + 2*p;
            size_t o0 = (size_t)(b*NC + c)*SP + s0 + tx*4;
            if constexpr (OUT_MODE == 0) {
                *(float4*)&out[o0]      = r0[p];
                *(float4*)&out[o0 + SP] = r1[p];
            } else {
                float4 a0 = *(const float4*)&aux[o0];
                float4 a1 = *(const float4*)&aux[o0 + SP];
                float4 w0 = make_float4(a0.x/(1.f+expf(-r0[p].x)), a0.y/(1.f+expf(-r0[p].y)),
                                        a0.z/(1.f+expf(-r0[p].z)), a0.w/(1.f+expf(-r0[p].w)));
                float4 w1 = make_float4(a1.x/(1.f+expf(-r1[p].x)), a1.y/(1.f+expf(-r1[p].y)),
                                        a1.z/(1.f+expf(-r1[p].z)), a1.w/(1.f+expf(-r1[p].w)));
                *(float4*)&out[o0]      = w0;
                *(float4*)&out[o0 + SP] = w1;
            }
        }
    }
}

// ---------------- axial attention, all 3 axes in one launch ----------------
__global__ void __launch_bounds__(160) k_attn(const float* __restrict__ qkv, float* __restrict__ osum) {
    __shared__ __align__(16) float sq[3840], sk[3840], sv[3840];   // [h][l][24]
    int axis = blockIdx.y;
    int blk = blockIdx.x;
    int b = blk / 1600, r = blk % 1600, a1 = r/40, a2 = r%40;
    int base, lst;
    if (axis == 0)      { base = a1*ND + a2;     lst = HW; }
    else if (axis == 1) { base = a1*HW + a2;     lst = ND; }
    else                { base = a1*HW + a2*ND;  lst = 1;  }
    int t = threadIdx.x;

    const float* qb = qkv + (size_t)(b*3)*4*SP*24;
    for (int f=t; f<2880; f+=160) {
        int which = f/960, rr = f%960, h = rr/240, r2 = rr%240, l = r2/6, u = r2%6;
        float4 val = *(const float4*)&qb[((size_t)(which*4+h)*SP + base + (size_t)l*lst)*24 + u*4];
        float* dst = (which==0) ? sq : ((which==1) ? sk : sv);
        *(float4*)&dst[h*960 + l*24 + u*4] = val;
    }
    __syncthreads();

    int h = t/40, i = t%40;
    float4 q[6];
    #pragma unroll
    for (int u=0;u<6;u++) q[u] = *(const float4*)&sq[h*960 + i*24 + u*4];

    const float scale = 0.20412414523193154f;
    float S[40];
    float mx = -1e30f;
    #pragma unroll
    for (int j=0;j<40;j++) {
        const float4* kp = (const float4*)&sk[h*960 + j*24];
        float s = 0.f;
        #pragma unroll
        for (int u=0;u<6;u++) {
            float4 kv = kp[u];
            s += q[u].x*kv.x + q[u].y*kv.y + q[u].z*kv.z + q[u].w*kv.w;
        }
        s *= scale;
        S[j] = s;
        mx = fmaxf(mx, s);
    }
    float sum = 0.f;
    #pragma unroll
    for (int j=0;j<40;j++) { S[j] = expf(S[j]-mx); sum += S[j]; }
    float inv = 1.f/sum;

    float4 o[6];
    #pragma unroll
    for (int u=0;u<6;u++) o[u] = make_float4(0.f,0.f,0.f,0.f);
    #pragma unroll
    for (int j=0;j<40;j++) {
        float p = S[j]*inv;
        const float4* vp = (const float4*)&sv[h*960 + j*24];
        #pragma unroll
        for (int u=0;u<6;u++) {
            float4 vv = vp[u];
            o[u].x += p*vv.x; o[u].y += p*vv.y; o[u].z += p*vv.z; o[u].w += p*vv.w;
        }
    }
    size_t ob = (size_t)axis*OSLAB + ((size_t)(b*4+h)*SP + base + (size_t)i*lst)*24;
    #pragma unroll
    for (int u=0;u<6;u++)
        *(float4*)&osum[ob + u*4] = o[u];
}

// ---------------- launch ----------------
extern "C" void kernel_launch(void* const* d_in, const int* in_sizes, int n_in,
                              void* d_out, int out_size) {
    const float* x      = (const float*)d_in[0];
    const float* pos    = (const float*)d_in[1];
    const float* qkv_w  = (const float*)d_in[2];
    const float* qkv_b  = (const float*)d_in[3];
    const float* lp1_w  = (const float*)d_in[4];
    const float* lp1_b  = (const float*)d_in[5];
    const float* lp2_w  = (const float*)d_in[6];
    const float* lp2_b  = (const float*)d_in[7];
    const float* mod1_w = (const float*)d_in[8];
    const float* mod1_b = (const float*)d_in[9];
    const float* mod2_w = (const float*)d_in[10];
    const float* mod2_b = (const float*)d_in[11];
    // d_in[12..16]: pa_w, pa_b, R6_d, R6_h, R6_w — mathematically unused
    const float* proj_w = (const float*)d_in[17];
    const float* proj_b = (const float*)d_in[18];
    float* out = (float*)d_out;

    float *buf1, *buf2, *xmod, *qkvp, *osum;
    cudaGetSymbolAddress((void**)&buf1, g_buf1);
    cudaGetSymbolAddress((void**)&buf2, g_buf2);
    cudaGetSymbolAddress((void**)&xmod, g_xmod);
    cudaGetSymbolAddress((void**)&qkvp, g_qkv);
    cudaGetSymbolAddress((void**)&osum, g_osum);

    const int GS = (12288 + 9600) * 4;   // 87552 B dynamic smem for gemms
    const int CS = CONV_SMEM_F * 4;      // 63488 B for conv
    cudaFuncSetAttribute(k_gemm<1,0>, cudaFuncAttributeMaxDynamicSharedMemorySize, GS);
    cudaFuncSetAttribute(k_gemm<0,0>, cudaFuncAttributeMaxDynamicSharedMemorySize, GS);
    cudaFuncSetAttribute(k_gemm<1,1>, cudaFuncAttributeMaxDynamicSharedMemorySize, GS);
    cudaFuncSetAttribute(k_gemm<0,2>, cudaFuncAttributeMaxDynamicSharedMemorySize, GS);
    cudaFuncSetAttribute(k_gemm<2,0>, cudaFuncAttributeMaxDynamicSharedMemorySize, GS);
    cudaFuncSetAttribute(k_conv3_mma, cudaFuncAttributeMaxDynamicSharedMemorySize, CS);

    // prep: transpose input, split conv weights into tf32 hi/lo
    k_xt<<<dim3(1000,3,2), 256>>>(pos);
    k_wc3prep<<<(2*27*NC*NC + 255)/256, 256>>>(lp1_w);
    // conv3 on tensor cores (3xTF32, writes g_buf1 with bias)
    k_conv3_mma<<<1000, 256, CS>>>(lp1_b);
    k_stats<<<NB*NC, 256>>>(buf1);
    k_gemm<1,0><<<dim3(500,1,2), 256, GS>>>(buf1, lp2_w, lp2_b, buf2, nullptr);   // local
    k_gemm<0,0><<<dim3(500,1,2), 256, GS>>>(buf2, mod1_w, mod1_b, buf1, nullptr);
    k_stats<<<NB*NC, 256>>>(buf1);
    k_gemm<1,1><<<dim3(500,1,2), 256, GS>>>(buf1, mod2_w, mod2_b, xmod, x);       // x_mod
    k_gemm<0,2><<<dim3(500,3,2), 256, GS>>>(xmod, qkv_w, qkv_b, qkvp, nullptr);
    k_attn<<<dim3(3200,3), 160>>>(qkvp, osum);
    k_gemm<2,0><<<dim3(500,1,2), 256, GS>>>(osum, proj_w, proj_b, out, nullptr);
}

// round 11
// speedup vs baseline: 1.9234x; 1.3105x over previous
#include <cuda_runtime.h>
#include <math.h>
#include <cstdint>

#define NB 2
#define NC 96
#define ND 40
#define HW 1600
#define SP 64000   // 40*40*40

typedef unsigned long long ull;

// ---------------- scratch (no allocs allowed) ----------------
__device__ float g_buf1[NB*NC*SP];
__device__ float g_buf2[NB*NC*SP];
__device__ float g_xmod[NB*NC*SP];
__device__ float g_qkv [NB*3*4*SP*24];    // [b][which][head][S][24]
__device__ float g_osum[3*NB*4*SP*24];    // [axis][b][head][S][24]
__device__ float g_stats[NB*NC*2];
__device__ double g_part[NB*NC*8*2];
__device__ uint32_t g_xth[NB*SP*48];      // pos_emb bf16-hi pairs: [b][s][ci_pair]
__device__ uint32_t g_xtl[NB*SP*48];      // bf16-lo residual pairs
__device__ uint32_t g_wpk[27*2*96*48];    // conv3 W: [tap][prec][co][ci_pair]

#define OSLAB ((size_t)NB*4*SP*24)

// ---------------- packed fp32x2 helpers ----------------
__device__ __forceinline__ void ffma2(ull &acc, ull w, ull x) {
    asm("fma.rn.f32x2 %0, %1, %2, %0;" : "+l"(acc) : "l"(w), "l"(x));
}
__device__ __forceinline__ ull bcast2(float x) {
    ull r;
    asm("mov.b64 %0, {%1, %1};" : "=l"(r) : "f"(x));
    return r;
}
__device__ __forceinline__ float2 unpack2(ull v) {
    float2 r;
    asm("mov.b64 {%0, %1}, %2;" : "=f"(r.x), "=f"(r.y) : "l"(v));
    return r;
}

// ---------------- bf16 helpers ----------------
// pack: even element -> low 16, odd -> high 16
__device__ __forceinline__ uint32_t pack_bf16(float v0, float v1) {
    uint32_t d;
    asm("cvt.rn.bf16x2.f32 %0, %1, %2;" : "=r"(d) : "f"(v1), "f"(v0));
    return d;
}
__device__ __forceinline__ void split_pair(float v0, float v1, uint32_t &hi, uint32_t &lo) {
    hi = pack_bf16(v0, v1);
    float h0 = __uint_as_float(hi << 16);
    float h1 = __uint_as_float(hi & 0xFFFF0000u);
    lo = pack_bf16(v0 - h0, v1 - h1);
}
// D(16x8,f32) += A(16x16,bf16,row) * B(16x8,bf16,col)
__device__ __forceinline__ void mmab(float* d, const uint32_t* a, uint32_t b0, uint32_t b1) {
    asm volatile("mma.sync.aligned.m16n8k16.row.col.f32.bf16.bf16.f32 "
        "{%0,%1,%2,%3}, {%4,%5,%6,%7}, {%8,%9}, {%0,%1,%2,%3};"
        : "+f"(d[0]), "+f"(d[1]), "+f"(d[2]), "+f"(d[3])
        : "r"(a[0]), "r"(a[1]), "r"(a[2]), "r"(a[3]), "r"(b0), "r"(b1));
}

// ---------------- prep: transpose pos_emb + bf16 hi/lo split ----------------
__global__ void __launch_bounds__(256) k_xt(const float* __restrict__ x) {
    __shared__ float tile[32][65];
    int sblk = blockIdx.x, cb = blockIdx.y, b = blockIdx.z;
    int t = threadIdx.x;
    for (int i=t; i<2048; i+=256) {
        int c = i>>6, s = i&63;
        tile[c][s] = x[(size_t)(b*NC + cb*32 + c)*SP + sblk*64 + s];
    }
    __syncthreads();
    for (int i=t; i<1024; i+=256) {
        int s = i>>4, p = i&15;
        float v0 = tile[2*p][s], v1 = tile[2*p+1][s];
        uint32_t hi, lo;
        split_pair(v0, v1, hi, lo);
        size_t di = ((size_t)b*SP + sblk*64 + s)*48 + cb*16 + p;
        g_xth[di] = hi;
        g_xtl[di] = lo;
    }
}

// ---------------- prep: conv3 weights -> bf16 hi/lo pairs [tap][prec][co][pair] ----------------
__global__ void k_wprep(const float* __restrict__ w) {
    int idx = blockIdx.x*256 + threadIdx.x;
    if (idx >= 27*96*48) return;
    int tap = idx/(96*48);
    int rem = idx%(96*48);
    int co = rem/48, p = rem%48;
    float v0 = w[((size_t)co*NC + 2*p  )*27 + tap];
    float v1 = w[((size_t)co*NC + 2*p+1)*27 + tap];
    uint32_t hi, lo;
    split_pair(v0, v1, hi, lo);
    g_wpk[(((size_t)tap*2+0)*96 + co)*48 + p] = hi;
    g_wpk[(((size_t)tap*2+1)*96 + co)*48 + p] = lo;
}

// ---------------- conv 3x3x3 circular via mma.sync bf16 (3xBF16) ----------------
// Block: 128 consecutive (b,s) rows x 96 co, 27 tap-stages, all 96 ci resident.
// smem u32: A_hi[128][52] @0, A_lo @6656, W_hi[96][52] @13312, W_lo @18304. 93184 B.
#define CA_LO 6656
#define CW_HI 13312
#define CW_LO 18304
#define CONV_U32 23296

__global__ void __launch_bounds__(256) k_conv3_bf16(const float* __restrict__ bias) {
    extern __shared__ __align__(16) uint32_t su[];
    int t = threadIdx.x;
    int wid = t>>5, lid = t&31;
    int g8 = lid>>2, t4 = lid&3;
    int wm = wid>>1, wn = wid&1;
    int gs0 = blockIdx.x * 128;
    int b = gs0 / SP, sbase = gs0 % SP;

    // per-thread A staging coords: row = t>>1, half = t&1
    int row = t>>1, half = t&1;
    int s = sbase + row;
    int dz = s/1600, rr = s - dz*1600, hz = rr/40, wz = rr - hz*40;

    float d[2][6][4];
    #pragma unroll
    for (int a=0;a<2;a++)
        #pragma unroll
        for (int n=0;n<6;n++)
            #pragma unroll
            for (int k=0;k<4;k++) d[a][n][k] = 0.f;

    for (int tap=0; tap<27; tap++) {
        int kd = tap/9, kh = (tap/3)%3, kw = tap%3;
        // ---- stage A (hi/lo): one row-half per thread, 6+6 uint4 copies ----
        {
            int dd = dz + kd - 1; if (dd<0) dd+=ND; else if (dd>=ND) dd-=ND;
            int hh = hz + kh - 1; if (hh<0) hh+=ND; else if (hh>=ND) hh-=ND;
            int ww = wz + kw - 1; if (ww<0) ww+=ND; else if (ww>=ND) ww-=ND;
            size_t src = ((size_t)b*SP + dd*HW + hh*ND + ww)*48 + half*24;
            const uint4* sh = (const uint4*)&g_xth[src];
            const uint4* sl = (const uint4*)&g_xtl[src];
            uint4* dh = (uint4*)&su[row*52 + half*24];
            uint4* dl = (uint4*)&su[CA_LO + row*52 + half*24];
            #pragma unroll
            for (int j=0;j<6;j++) { dh[j] = sh[j]; dl[j] = sl[j]; }
        }
        // ---- stage W (hi/lo): 2304 uint4 ----
        #pragma unroll
        for (int it=0; it<9; it++) {
            int i = t + it*256;
            int prec = i/1152, r2 = i - prec*1152;
            int co = r2/12, j = r2 - co*12;
            *(uint4*)&su[CW_HI + prec*4992 + co*52 + j*4] =
                *(const uint4*)&g_wpk[(((size_t)tap*2+prec)*96 + co)*48 + j*4];
        }
        __syncthreads();

        // ---- compute: 6 k16-steps x 6 n-tiles x 2 m-subtiles x 3 passes ----
        #pragma unroll
        for (int ks=0; ks<6; ks++) {
            uint32_t ah[2][4], al[2][4];
            #pragma unroll
            for (int sub=0; sub<2; sub++) {
                int base = (wm*32 + sub*16 + g8)*52 + ks*8 + t4;
                ah[sub][0] = su[base];
                ah[sub][1] = su[base + 8*52];
                ah[sub][2] = su[base + 4];
                ah[sub][3] = su[base + 8*52 + 4];
                al[sub][0] = su[CA_LO + base];
                al[sub][1] = su[CA_LO + base + 8*52];
                al[sub][2] = su[CA_LO + base + 4];
                al[sub][3] = su[CA_LO + base + 8*52 + 4];
            }
            #pragma unroll
            for (int nt=0; nt<6; nt++) {
                int wb = CW_HI + (wn*48 + nt*8 + g8)*52 + ks*8 + t4;
                uint32_t bh0 = su[wb],        bh1 = su[wb+4];
                uint32_t bl0 = su[wb+4992],   bl1 = su[wb+4992+4];
                #pragma unroll
                for (int sub=0; sub<2; sub++) {
                    mmab(d[sub][nt], ah[sub], bh0, bh1);
                    mmab(d[sub][nt], al[sub], bh0, bh1);
                    mmab(d[sub][nt], ah[sub], bl0, bl1);
                }
            }
        }
        __syncthreads();
    }

    // ---- epilogue: d frags -> s_out[96 co][132 pad] -> coalesced gmem ----
    float* s_out = (float*)su;
    #pragma unroll
    for (int sub=0; sub<2; sub++) {
        int row0 = wm*32 + sub*16 + g8;
        #pragma unroll
        for (int nt=0; nt<6; nt++) {
            int c0 = wn*48 + nt*8 + t4*2;
            s_out[(c0  )*132 + row0]     = d[sub][nt][0];
            s_out[(c0+1)*132 + row0]     = d[sub][nt][1];
            s_out[(c0  )*132 + row0 + 8] = d[sub][nt][2];
            s_out[(c0+1)*132 + row0 + 8] = d[sub][nt][3];
        }
    }
    __syncthreads();
    for (int i=t; i<3072; i+=256) {
        int co = i>>5, s4 = (i&31)*4;
        float4 v = *(const float4*)&s_out[co*132 + s4];
        float bb = bias[co];
        v.x += bb; v.y += bb; v.z += bb; v.w += bb;
        *(float4*)&g_buf1[(size_t)(b*NC+co)*SP + sbase + s4] = v;
    }
}

// ---------------- instance-norm stats: two-phase ----------------
__global__ void __launch_bounds__(256) k_stats1(const float* __restrict__ x) {
    __shared__ double ss[256], ss2[256];
    int bc = blockIdx.x, ch = blockIdx.y, t = threadIdx.x;
    const float* p = x + (size_t)bc*SP + ch*8000;
    double s=0.0, s2=0.0;
    for (int i=t; i<8000; i+=256) { double v = p[i]; s += v; s2 += v*v; }
    ss[t]=s; ss2[t]=s2; __syncthreads();
    for (int o=128;o>0;o>>=1){ if(t<o){ss[t]+=ss[t+o]; ss2[t]+=ss2[t+o];} __syncthreads(); }
    if (t==0) {
        g_part[(bc*8+ch)*2  ] = ss[0];
        g_part[(bc*8+ch)*2+1] = ss2[0];
    }
}
__global__ void k_stats2() {
    int bc = threadIdx.x;
    if (bc >= NB*NC) return;
    double s=0.0, s2=0.0;
    for (int c=0;c<8;c++) { s += g_part[(bc*8+c)*2]; s2 += g_part[(bc*8+c)*2+1]; }
    double mu  = s/(double)SP;
    double var = s2/(double)SP - mu*mu;
    g_stats[bc*2]   = (float)mu;
    g_stats[bc*2+1] = (float)(1.0/sqrt(var + 1e-5));
}

// ---------------- fused conv1x1 GEMM, full-K resident in smem ----------------
// IN_MODE:  0 plain [b][c][S]   1 IN+gelu on load   2 sum of 3 attn slabs [axis][b][h][S][24]
// OUT_MODE: 0 plain [b][c][S]   1 sigmoid(res)*aux  2 QKV head layout, which = blockIdx.y
template<int IN_MODE, int OUT_MODE>
__global__ void __launch_bounds__(256) k_gemm(const float* __restrict__ in, const float* __restrict__ W,
                                              const float* __restrict__ bias, float* __restrict__ out,
                                              const float* __restrict__ aux) {
    extern __shared__ __align__(16) float s_mem[];
    float* s_x = s_mem;            // [ci=96][s=128]
    float* s_w = s_mem + 12288;    // [ci=96][co pad 100]
    int b = blockIdx.z, s0 = blockIdx.x*128, grp = blockIdx.y;
    int co0 = grp*96;
    int t = threadIdx.x, tx = t & 31, ty = t >> 5;

    if constexpr (IN_MODE == 2) {
        for (int f=t; f<3072; f+=256) {
            int h = f/768, rem = f%768, s = rem/6, u = rem%6;
            size_t gi = ((size_t)(b*4+h)*SP + s0 + s)*24 + u*4;
            float4 a = *(const float4*)&in[gi];
            float4 c = *(const float4*)&in[gi + OSLAB];
            float4 e = *(const float4*)&in[gi + 2*OSLAB];
            int cbase = (h*24 + u*4)*128 + s;
            s_x[cbase      ] = a.x + c.x + e.x;
            s_x[cbase + 128] = a.y + c.y + e.y;
            s_x[cbase + 256] = a.z + c.z + e.z;
            s_x[cbase + 384] = a.w + c.w + e.w;
        }
    } else {
        for (int idx=t; idx<3072; idx+=256) {
            int ci = idx>>5, s4 = (idx&31)*4;
            float4 v = *(const float4*)&in[(size_t)(b*NC+ci)*SP + s0 + s4];
            if constexpr (IN_MODE == 1) {
                int bc = b*NC+ci;
                float mu = g_stats[bc*2], rs = g_stats[bc*2+1];
                v.x = (v.x-mu)*rs; v.x = 0.5f*v.x*(1.0f+erff(v.x*0.70710678118654752f));
                v.y = (v.y-mu)*rs; v.y = 0.5f*v.y*(1.0f+erff(v.y*0.70710678118654752f));
                v.z = (v.z-mu)*rs; v.z = 0.5f*v.z*(1.0f+erff(v.z*0.70710678118654752f));
                v.w = (v.w-mu)*rs; v.w = 0.5f*v.w*(1.0f+erff(v.w*0.70710678118654752f));
            }
            *(float4*)&s_x[ci*128 + s4] = v;
        }
    }
    for (int idx=t; idx<2304; idx+=256) {
        int co = idx/24, ci4 = (idx%24)*4;
        float4 w = *(const float4*)&W[(size_t)(co0+co)*NC + ci4];
        s_w[(ci4+0)*100 + co] = w.x;
        s_w[(ci4+1)*100 + co] = w.y;
        s_w[(ci4+2)*100 + co] = w.z;
        s_w[(ci4+3)*100 + co] = w.w;
    }
    __syncthreads();

    ull acc[6][4];
    #pragma unroll
    for (int p=0;p<6;p++)
        #pragma unroll
        for (int j=0;j<4;j++) acc[p][j] = 0ull;

    const float* xrow = s_x + tx*4;
    const float* wrow = s_w + ty*12;
    #pragma unroll 8
    for (int ci=0; ci<96; ci++) {
        float4 xv = *(const float4*)(xrow + ci*128);
        ull xb[4] = { bcast2(xv.x), bcast2(xv.y), bcast2(xv.z), bcast2(xv.w) };
        const float* wp = wrow + ci*100;
        ulonglong2 w01 = *(const ulonglong2*)(wp);
        ulonglong2 w23 = *(const ulonglong2*)(wp+4);
        ulonglong2 w45 = *(const ulonglong2*)(wp+8);
        #pragma unroll
        for (int j=0;j<4;j++) {
            ffma2(acc[0][j], w01.x, xb[j]);
            ffma2(acc[1][j], w01.y, xb[j]);
            ffma2(acc[2][j], w23.x, xb[j]);
            ffma2(acc[3][j], w23.y, xb[j]);
            ffma2(acc[4][j], w45.x, xb[j]);
            ffma2(acc[5][j], w45.y, xb[j]);
        }
    }

    float4 r0[6], r1[6];
    #pragma unroll
    for (int p=0;p<6;p++) {
        int c = ty*12 + 2*p;
        float b0 = bias[co0 + c], b1 = bias[co0 + c + 1];
        float2 v[4];
        #pragma unroll
        for (int j=0;j<4;j++) { v[j] = unpack2(acc[p][j]); v[j].x += b0; v[j].y += b1; }
        r0[p] = make_float4(v[0].x, v[1].x, v[2].x, v[3].x);
        r1[p] = make_float4(v[0].y, v[1].y, v[2].y, v[3].y);
    }

    if constexpr (OUT_MODE == 2) {
        __syncthreads();
        float* s_out = s_mem;
        #pragma unroll
        for (int p=0;p<6;p++) {
            int c = ty*12 + 2*p;
            *(float4*)&s_out[c*128 + tx*4]     = r0[p];
            *(float4*)&s_out[(c+1)*128 + tx*4] = r1[p];
        }
        __syncthreads();
        float* ob = out + ((size_t)(b*3 + grp)*4)*SP*24;
        for (int f=t; f<3072; f+=256) {
            int h = f/768, rem = f%768, s = rem/6, u = rem%6;
            float4 r;
            r.x = s_out[(h*24+u*4+0)*128 + s];
            r.y = s_out[(h*24+u*4+1)*128 + s];
            r.z = s_out[(h*24+u*4+2)*128 + s];
            r.w = s_out[(h*24+u*4+3)*128 + s];
            *(float4*)&ob[((size_t)h*SP + s0 + s)*24 + u*4] = r;
        }
    } else {
        #pragma unroll
        for (int p=0;p<6;p++) {
            int c = ty*12 + 2*p;
            size_t o0 = (size_t)(b*NC + c)*SP + s0 + tx*4;
            if constexpr (OUT_MODE == 0) {
                *(float4*)&out[o0]      = r0[p];
                *(float4*)&out[o0 + SP] = r1[p];
            } else {
                float4 a0 = *(const float4*)&aux[o0];
                float4 a1 = *(const float4*)&aux[o0 + SP];
                float4 w0 = make_float4(a0.x/(1.f+expf(-r0[p].x)), a0.y/(1.f+expf(-r0[p].y)),
                                        a0.z/(1.f+expf(-r0[p].z)), a0.w/(1.f+expf(-r0[p].w)));
                float4 w1 = make_float4(a1.x/(1.f+expf(-r1[p].x)), a1.y/(1.f+expf(-r1[p].y)),
                                        a1.z/(1.f+expf(-r1[p].z)), a1.w/(1.f+expf(-r1[p].w)));
                *(float4*)&out[o0]      = w0;
                *(float4*)&out[o0 + SP] = w1;
            }
        }
    }
}

// ---------------- axial attention, all 3 axes in one launch ----------------
__global__ void __launch_bounds__(160) k_attn(const float* __restrict__ qkv, float* __restrict__ osum) {
    __shared__ __align__(16) float sq[3840], sk[3840], sv[3840];   // [h][l][24]
    int axis = blockIdx.y;
    int blk = blockIdx.x;
    int b = blk / 1600, r = blk % 1600, a1 = r/40, a2 = r%40;
    int base, lst;
    if (axis == 0)      { base = a1*ND + a2;     lst = HW; }
    else if (axis == 1) { base = a1*HW + a2;     lst = ND; }
    else                { base = a1*HW + a2*ND;  lst = 1;  }
    int t = threadIdx.x;

    const float* qb = qkv + (size_t)(b*3)*4*SP*24;
    for (int f=t; f<2880; f+=160) {
        int which = f/960, rr = f%960, h = rr/240, r2 = rr%240, l = r2/6, u = r2%6;
        float4 val = *(const float4*)&qb[((size_t)(which*4+h)*SP + base + (size_t)l*lst)*24 + u*4];
        float* dst = (which==0) ? sq : ((which==1) ? sk : sv);
        *(float4*)&dst[h*960 + l*24 + u*4] = val;
    }
    __syncthreads();

    int h = t/40, i = t%40;
    float4 q[6];
    #pragma unroll
    for (int u=0;u<6;u++) q[u] = *(const float4*)&sq[h*960 + i*24 + u*4];

    const float scale = 0.20412414523193154f;
    float S[40];
    float mx = -1e30f;
    #pragma unroll
    for (int j=0;j<40;j++) {
        const float4* kp = (const float4*)&sk[h*960 + j*24];
        float s = 0.f;
        #pragma unroll
        for (int u=0;u<6;u++) {
            float4 kv = kp[u];
            s += q[u].x*kv.x + q[u].y*kv.y + q[u].z*kv.z + q[u].w*kv.w;
        }
        s *= scale;
        S[j] = s;
        mx = fmaxf(mx, s);
    }
    float sum = 0.f;
    #pragma unroll
    for (int j=0;j<40;j++) { S[j] = expf(S[j]-mx); sum += S[j]; }
    float inv = 1.f/sum;

    float4 o[6];
    #pragma unroll
    for (int u=0;u<6;u++) o[u] = make_float4(0.f,0.f,0.f,0.f);
    #pragma unroll
    for (int j=0;j<40;j++) {
        float p = S[j]*inv;
        const float4* vp = (const float4*)&sv[h*960 + j*24];
        #pragma unroll
        for (int u=0;u<6;u++) {
            float4 vv = vp[u];
            o[u].x += p*vv.x; o[u].y += p*vv.y; o[u].z += p*vv.z; o[u].w += p*vv.w;
        }
    }
    size_t ob = (size_t)axis*OSLAB + ((size_t)(b*4+h)*SP + base + (size_t)i*lst)*24;
    #pragma unroll
    for (int u=0;u<6;u++)
        *(float4*)&osum[ob + u*4] = o[u];
}

// ---------------- launch ----------------
extern "C" void kernel_launch(void* const* d_in, const int* in_sizes, int n_in,
                              void* d_out, int out_size) {
    const float* x      = (const float*)d_in[0];
    const float* pos    = (const float*)d_in[1];
    const float* qkv_w  = (const float*)d_in[2];
    const float* qkv_b  = (const float*)d_in[3];
    const float* lp1_w  = (const float*)d_in[4];
    const float* lp1_b  = (const float*)d_in[5];
    const float* lp2_w  = (const float*)d_in[6];
    const float* lp2_b  = (const float*)d_in[7];
    const float* mod1_w = (const float*)d_in[8];
    const float* mod1_b = (const float*)d_in[9];
    const float* mod2_w = (const float*)d_in[10];
    const float* mod2_b = (const float*)d_in[11];
    // d_in[12..16]: pa_w, pa_b, R6_d, R6_h, R6_w — mathematically unused
    const float* proj_w = (const float*)d_in[17];
    const float* proj_b = (const float*)d_in[18];
    float* out = (float*)d_out;

    float *buf1, *buf2, *xmod, *qkvp, *osum;
    cudaGetSymbolAddress((void**)&buf1, g_buf1);
    cudaGetSymbolAddress((void**)&buf2, g_buf2);
    cudaGetSymbolAddress((void**)&xmod, g_xmod);
    cudaGetSymbolAddress((void**)&qkvp, g_qkv);
    cudaGetSymbolAddress((void**)&osum, g_osum);

    const int GS = (12288 + 9600) * 4;   // 87552 B dynamic smem for gemms
    const int CS = CONV_U32 * 4;         // 93184 B for conv
    cudaFuncSetAttribute(k_gemm<1,0>, cudaFuncAttributeMaxDynamicSharedMemorySize, GS);
    cudaFuncSetAttribute(k_gemm<0,0>, cudaFuncAttributeMaxDynamicSharedMemorySize, GS);
    cudaFuncSetAttribute(k_gemm<1,1>, cudaFuncAttributeMaxDynamicSharedMemorySize, GS);
    cudaFuncSetAttribute(k_gemm<0,2>, cudaFuncAttributeMaxDynamicSharedMemorySize, GS);
    cudaFuncSetAttribute(k_gemm<2,0>, cudaFuncAttributeMaxDynamicSharedMemorySize, GS);
    cudaFuncSetAttribute(k_conv3_bf16, cudaFuncAttributeMaxDynamicSharedMemorySize, CS);

    // prep: transpose input + bf16 hi/lo split; pack conv weights
    k_xt<<<dim3(1000,3,2), 256>>>(pos);
    k_wprep<<<(27*96*48 + 255)/256, 256>>>(lp1_w);
    // conv3 on tensor cores (3xBF16, writes g_buf1 with bias)
    k_conv3_bf16<<<1000, 256, CS>>>(lp1_b);
    k_stats1<<<dim3(NB*NC,8), 256>>>(buf1);
    k_stats2<<<1, NB*NC>>>();
    k_gemm<1,0><<<dim3(500,1,2), 256, GS>>>(buf1, lp2_w, lp2_b, buf2, nullptr);   // local
    k_gemm<0,0><<<dim3(500,1,2), 256, GS>>>(buf2, mod1_w, mod1_b, buf1, nullptr);
    k_stats1<<<dim3(NB*NC,8), 256>>>(buf1);
    k_stats2<<<1, NB*NC>>>();
    k_gemm<1,1><<<dim3(500,1,2), 256, GS>>>(buf1, mod2_w, mod2_b, xmod, x);       // x_mod
    k_gemm<0,2><<<dim3(500,3,2), 256, GS>>>(xmod, qkv_w, qkv_b, qkvp, nullptr);
    k_attn<<<dim3(3200,3), 160>>>(qkvp, osum);
    k_gemm<2,0><<<dim3(500,1,2), 256, GS>>>(osum, proj_w, proj_b, out, nullptr);
}

// round 13
// speedup vs baseline: 2.2437x; 1.1665x over previous
#include <cuda_runtime.h>
#include <math.h>
#include <cstdint>

#define NB 2
#define NC 96
#define ND 40
#define HW 1600
#define SP 64000   // 40*40*40

// ---------------- scratch (no allocs allowed) ----------------
__device__ float g_buf1[NB*NC*SP];
__device__ float g_buf2[NB*NC*SP];
__device__ float g_xmod[NB*NC*SP];
__device__ float g_qkv [NB*3*4*SP*24];    // [b][which][head][S][24]
__device__ float g_osum[3*NB*4*SP*24];    // [axis][b][head][S][24]
__device__ float g_stats[NB*NC*2];
__device__ double g_part[NB*NC*8*2];
__device__ uint32_t g_xth[NB*SP*48];      // pos_emb bf16-hi pairs: [b][s][ci_pair]
__device__ uint32_t g_xtl[NB*SP*48];      // bf16-lo residual pairs
__device__ uint32_t g_wpk[27*2*96*48];    // conv3 W: [tap][prec][co][ci_pair]

#define OSLAB ((size_t)NB*4*SP*24)

// ---------------- bf16 helpers ----------------
// pack: even element -> low 16, odd -> high 16
__device__ __forceinline__ uint32_t pack_bf16(float v0, float v1) {
    uint32_t d;
    asm("cvt.rn.bf16x2.f32 %0, %1, %2;" : "=r"(d) : "f"(v1), "f"(v0));
    return d;
}
__device__ __forceinline__ void split_pair(float v0, float v1, uint32_t &hi, uint32_t &lo) {
    hi = pack_bf16(v0, v1);
    float h0 = __uint_as_float(hi << 16);
    float h1 = __uint_as_float(hi & 0xFFFF0000u);
    lo = pack_bf16(v0 - h0, v1 - h1);
}
// D(16x8,f32) += A(16x16,bf16,row) * B(16x8,bf16,col)
__device__ __forceinline__ void mmab(float* d, const uint32_t* a, uint32_t b0, uint32_t b1) {
    asm volatile("mma.sync.aligned.m16n8k16.row.col.f32.bf16.bf16.f32 "
        "{%0,%1,%2,%3}, {%4,%5,%6,%7}, {%8,%9}, {%0,%1,%2,%3};"
        : "+f"(d[0]), "+f"(d[1]), "+f"(d[2]), "+f"(d[3])
        : "r"(a[0]), "r"(a[1]), "r"(a[2]), "r"(a[3]), "r"(b0), "r"(b1));
}

// ---------------- prep: transpose pos_emb + bf16 hi/lo split ----------------
__global__ void __launch_bounds__(256) k_xt(const float* __restrict__ x) {
    __shared__ float tile[32][65];
    int sblk = blockIdx.x, cb = blockIdx.y, b = blockIdx.z;
    int t = threadIdx.x;
    for (int i=t; i<2048; i+=256) {
        int c = i>>6, s = i&63;
        tile[c][s] = x[(size_t)(b*NC + cb*32 + c)*SP + sblk*64 + s];
    }
    __syncthreads();
    for (int i=t; i<1024; i+=256) {
        int s = i>>4, p = i&15;
        float v0 = tile[2*p][s], v1 = tile[2*p+1][s];
        uint32_t hi, lo;
        split_pair(v0, v1, hi, lo);
        size_t di = ((size_t)b*SP + sblk*64 + s)*48 + cb*16 + p;
        g_xth[di] = hi;
        g_xtl[di] = lo;
    }
}

// ---------------- prep: conv3 weights -> bf16 hi/lo pairs [tap][prec][co][pair] ----------------
__global__ void k_wprep(const float* __restrict__ w) {
    int idx = blockIdx.x*256 + threadIdx.x;
    if (idx >= 27*96*48) return;
    int tap = idx/(96*48);
    int rem = idx%(96*48);
    int co = rem/48, p = rem%48;
    float v0 = w[((size_t)co*NC + 2*p  )*27 + tap];
    float v1 = w[((size_t)co*NC + 2*p+1)*27 + tap];
    uint32_t hi, lo;
    split_pair(v0, v1, hi, lo);
    g_wpk[(((size_t)tap*2+0)*96 + co)*48 + p] = hi;
    g_wpk[(((size_t)tap*2+1)*96 + co)*48 + p] = lo;
}

// ---------------- conv 3x3x3 circular via mma.sync bf16 (3xBF16) ----------------
// Block: 128 consecutive (b,s) rows x 96 co, 27 tap-stages, all 96 ci resident.
// smem u32: A_hi[128][52] @0, A_lo @6656, W_hi[96][52] @13312, W_lo @18304. 93184 B.
#define CA_LO 6656
#define CW_HI 13312
#define CW_LO 18304
#define CONV_U32 23296

__global__ void __launch_bounds__(256) k_conv3_bf16(const float* __restrict__ bias) {
    extern __shared__ __align__(16) uint32_t su[];
    int t = threadIdx.x;
    int wid = t>>5, lid = t&31;
    int g8 = lid>>2, t4 = lid&3;
    int wm = wid>>1, wn = wid&1;
    int gs0 = blockIdx.x * 128;
    int b = gs0 / SP, sbase = gs0 % SP;

    int row = t>>1, half = t&1;
    int s = sbase + row;
    int dz = s/1600, rr = s - dz*1600, hz = rr/40, wz = rr - hz*40;

    float d[2][6][4];
    #pragma unroll
    for (int a=0;a<2;a++)
        #pragma unroll
        for (int n=0;n<6;n++)
            #pragma unroll
            for (int k=0;k<4;k++) d[a][n][k] = 0.f;

    for (int tap=0; tap<27; tap++) {
        int kd = tap/9, kh = (tap/3)%3, kw = tap%3;
        {
            int dd = dz + kd - 1; if (dd<0) dd+=ND; else if (dd>=ND) dd-=ND;
            int hh = hz + kh - 1; if (hh<0) hh+=ND; else if (hh>=ND) hh-=ND;
            int ww = wz + kw - 1; if (ww<0) ww+=ND; else if (ww>=ND) ww-=ND;
            size_t src = ((size_t)b*SP + dd*HW + hh*ND + ww)*48 + half*24;
            const uint4* sh = (const uint4*)&g_xth[src];
            const uint4* sl = (const uint4*)&g_xtl[src];
            uint4* dh = (uint4*)&su[row*52 + half*24];
            uint4* dl = (uint4*)&su[CA_LO + row*52 + half*24];
            #pragma unroll
            for (int j=0;j<6;j++) { dh[j] = sh[j]; dl[j] = sl[j]; }
        }
        #pragma unroll
        for (int it=0; it<9; it++) {
            int i = t + it*256;
            int prec = i/1152, r2 = i - prec*1152;
            int co = r2/12, j = r2 - co*12;
            *(uint4*)&su[CW_HI + prec*4992 + co*52 + j*4] =
                *(const uint4*)&g_wpk[(((size_t)tap*2+prec)*96 + co)*48 + j*4];
        }
        __syncthreads();

        #pragma unroll
        for (int ks=0; ks<6; ks++) {
            uint32_t ah[2][4], al[2][4];
            #pragma unroll
            for (int sub=0; sub<2; sub++) {
                int base = (wm*32 + sub*16 + g8)*52 + ks*8 + t4;
                ah[sub][0] = su[base];
                ah[sub][1] = su[base + 8*52];
                ah[sub][2] = su[base + 4];
                ah[sub][3] = su[base + 8*52 + 4];
                al[sub][0] = su[CA_LO + base];
                al[sub][1] = su[CA_LO + base + 8*52];
                al[sub][2] = su[CA_LO + base + 4];
                al[sub][3] = su[CA_LO + base + 8*52 + 4];
            }
            #pragma unroll
            for (int nt=0; nt<6; nt++) {
                int wb = CW_HI + (wn*48 + nt*8 + g8)*52 + ks*8 + t4;
                uint32_t bh0 = su[wb],        bh1 = su[wb+4];
                uint32_t bl0 = su[wb+4992],   bl1 = su[wb+4992+4];
                #pragma unroll
                for (int sub=0; sub<2; sub++) {
                    mmab(d[sub][nt], ah[sub], bh0, bh1);
                    mmab(d[sub][nt], al[sub], bh0, bh1);
                    mmab(d[sub][nt], ah[sub], bl0, bl1);
                }
            }
        }
        __syncthreads();
    }

    float* s_out = (float*)su;
    #pragma unroll
    for (int sub=0; sub<2; sub++) {
        int row0 = wm*32 + sub*16 + g8;
        #pragma unroll
        for (int nt=0; nt<6; nt++) {
            int c0 = wn*48 + nt*8 + t4*2;
            s_out[(c0  )*132 + row0]     = d[sub][nt][0];
            s_out[(c0+1)*132 + row0]     = d[sub][nt][1];
            s_out[(c0  )*132 + row0 + 8] = d[sub][nt][2];
            s_out[(c0+1)*132 + row0 + 8] = d[sub][nt][3];
        }
    }
    __syncthreads();
    for (int i=t; i<3072; i+=256) {
        int co = i>>5, s4 = (i&31)*4;
        float4 v = *(const float4*)&s_out[co*132 + s4];
        float bb = bias[co];
        v.x += bb; v.y += bb; v.z += bb; v.w += bb;
        *(float4*)&g_buf1[(size_t)(b*NC+co)*SP + sbase + s4] = v;
    }
}

// ---------------- instance-norm stats: two-phase, fp32 accumulation ----------------
__global__ void __launch_bounds__(256) k_stats1(const float* __restrict__ x) {
    __shared__ double sd[256], sd2[256];
    int bc = blockIdx.x, ch = blockIdx.y, t = threadIdx.x;
    const float4* p = (const float4*)(x + (size_t)bc*SP + ch*8000);   // 2000 float4
    float s = 0.f, s2 = 0.f;
    for (int i=t; i<2000; i+=256) {
        float4 v = p[i];
        s  += (v.x + v.y) + (v.z + v.w);
        s2 += (v.x*v.x + v.y*v.y) + (v.z*v.z + v.w*v.w);
    }
    sd[t] = (double)s; sd2[t] = (double)s2;
    __syncthreads();
    for (int o=128;o>0;o>>=1){ if(t<o){sd[t]+=sd[t+o]; sd2[t]+=sd2[t+o];} __syncthreads(); }
    if (t==0) {
        g_part[(bc*8+ch)*2  ] = sd[0];
        g_part[(bc*8+ch)*2+1] = sd2[0];
    }
}
__global__ void k_stats2() {
    int bc = threadIdx.x;
    if (bc >= NB*NC) return;
    double s=0.0, s2=0.0;
    for (int c=0;c<8;c++) { s += g_part[(bc*8+c)*2]; s2 += g_part[(bc*8+c)*2+1]; }
    double mu  = s/(double)SP;
    double var = s2/(double)SP - mu*mu;
    g_stats[bc*2]   = (float)mu;
    g_stats[bc*2+1] = (float)(1.0/sqrt(var + 1e-5));
}

// ---------------- conv1x1 GEMM via mma.sync bf16 (3xBF16) ----------------
// Block: 128 s-rows x 96 co, K=96 ci. A stored [k-pair][s] stride 136 (==8 mod 32:
// frag loads conflict-free, staging STS.128 along s). W [k-pair][co] stride 104.
// IN_MODE:  0 plain [b][c][S]   1 IN+gelu on load   2 sum of 3 attn slabs [axis][b][h][S][24]
// OUT_MODE: 0 plain [b][c][S]   1 sigmoid(res)*aux  2 QKV head layout, which = blockIdx.y
#define GA_LO 6528
#define GW_HI 13056
#define GW_LO 18048
#define GEMM_U32 23040

template<int IN_MODE, int OUT_MODE>
__global__ void __launch_bounds__(256) k_gemm(const float* __restrict__ in, const float* __restrict__ W,
                                              const float* __restrict__ bias, float* __restrict__ out,
                                              const float* __restrict__ aux) {
    extern __shared__ __align__(16) uint32_t su[];
    int b = blockIdx.z, s0 = blockIdx.x*128, grp = blockIdx.y;
    int co0 = grp*96;
    int t = threadIdx.x;
    int wid = t>>5, lid = t&31;
    int g8 = lid>>2, t4 = lid&3;
    int wm = wid>>1, wn = wid&1;

    // ---- stage A: hi/lo bf16 pairs, layout [kp=48][s=128] stride 136 ----
    if constexpr (IN_MODE == 2) {
        #pragma unroll
        for (int it=0; it<12; it++) {
            int idx = t + it*256;            // 3072 = 24 ch-groups x 128 s
            int q = idx >> 7, s = idx & 127;
            int h = q/6, u = q%6;
            size_t gi = ((size_t)(b*4+h)*SP + s0 + s)*24 + u*4;
            float4 a = *(const float4*)&in[gi];
            float4 c = *(const float4*)&in[gi + OSLAB];
            float4 e = *(const float4*)&in[gi + 2*OSLAB];
            float4 v = make_float4(a.x+c.x+e.x, a.y+c.y+e.y, a.z+c.z+e.z, a.w+c.w+e.w);
            int p0 = q*2;
            uint32_t h0,l0,h1,l1;
            split_pair(v.x, v.y, h0, l0);
            split_pair(v.z, v.w, h1, l1);
            su[p0*136 + s]             = h0;
            su[(p0+1)*136 + s]         = h1;
            su[GA_LO + p0*136 + s]     = l0;
            su[GA_LO + (p0+1)*136 + s] = l1;
        }
    } else {
        #pragma unroll
        for (int it=0; it<6; it++) {
            int idx = t + it*256;            // 1536 = 48 pairs x 32 s-groups
            int p = idx>>5, sg = idx&31, s4 = sg*4;
            const float* b0p = in + (size_t)(b*NC + 2*p)*SP + s0 + s4;
            float4 v0 = *(const float4*)b0p;
            float4 v1 = *(const float4*)(b0p + SP);
            if constexpr (IN_MODE == 1) {
                int bc0 = b*NC + 2*p;
                float mu0 = g_stats[bc0*2],   rs0 = g_stats[bc0*2+1];
                float mu1 = g_stats[bc0*2+2], rs1 = g_stats[bc0*2+3];
                v0.x=(v0.x-mu0)*rs0; v0.x=0.5f*v0.x*(1.0f+erff(v0.x*0.70710678118654752f));
                v0.y=(v0.y-mu0)*rs0; v0.y=0.5f*v0.y*(1.0f+erff(v0.y*0.70710678118654752f));
                v0.z=(v0.z-mu0)*rs0; v0.z=0.5f*v0.z*(1.0f+erff(v0.z*0.70710678118654752f));
                v0.w=(v0.w-mu0)*rs0; v0.w=0.5f*v0.w*(1.0f+erff(v0.w*0.70710678118654752f));
                v1.x=(v1.x-mu1)*rs1; v1.x=0.5f*v1.x*(1.0f+erff(v1.x*0.70710678118654752f));
                v1.y=(v1.y-mu1)*rs1; v1.y=0.5f*v1.y*(1.0f+erff(v1.y*0.70710678118654752f));
                v1.z=(v1.z-mu1)*rs1; v1.z=0.5f*v1.z*(1.0f+erff(v1.z*0.70710678118654752f));
                v1.w=(v1.w-mu1)*rs1; v1.w=0.5f*v1.w*(1.0f+erff(v1.w*0.70710678118654752f));
            }
            uint4 H, L;
            split_pair(v0.x, v1.x, H.x, L.x);
            split_pair(v0.y, v1.y, H.y, L.y);
            split_pair(v0.z, v1.z, H.z, L.z);
            split_pair(v0.w, v1.w, H.w, L.w);
            *(uint4*)&su[p*136 + s4]         = H;
            *(uint4*)&su[GA_LO + p*136 + s4] = L;
        }
    }
    // ---- stage W: [kp=48][co=96] stride 104 (each float4 = 2 pairs; j covers 24) ----
    #pragma unroll
    for (int it=0; it<9; it++) {
        int idx = t + it*256;
        if (idx < 2304) {
            int co = idx/24, j = idx%24;
            float4 w = *(const float4*)&W[(size_t)(co0+co)*NC + j*4];
            uint32_t h0,l0,h1,l1;
            split_pair(w.x, w.y, h0, l0);
            split_pair(w.z, w.w, h1, l1);
            int kp0 = j*2;
            su[GW_HI + kp0*104 + co]     = h0;
            su[GW_HI + (kp0+1)*104 + co] = h1;
            su[GW_LO + kp0*104 + co]     = l0;
            su[GW_LO + (kp0+1)*104 + co] = l1;
        }
    }
    __syncthreads();

    // ---- compute: 6 k16-steps x 6 n-tiles x 2 m-subtiles x 3 passes ----
    float d[2][6][4];
    #pragma unroll
    for (int a=0;a<2;a++)
        #pragma unroll
        for (int n=0;n<6;n++)
            #pragma unroll
            for (int k=0;k<4;k++) d[a][n][k] = 0.f;

    #pragma unroll
    for (int ks=0; ks<6; ks++) {
        uint32_t ah[2][4], al[2][4];
        #pragma unroll
        for (int sub=0; sub<2; sub++) {
            int rb = wm*32 + sub*16 + g8;
            int base = (ks*8 + t4)*136 + rb;
            ah[sub][0] = su[base];
            ah[sub][1] = su[base + 8];
            ah[sub][2] = su[base + 4*136];
            ah[sub][3] = su[base + 4*136 + 8];
            al[sub][0] = su[GA_LO + base];
            al[sub][1] = su[GA_LO + base + 8];
            al[sub][2] = su[GA_LO + base + 4*136];
            al[sub][3] = su[GA_LO + base + 4*136 + 8];
        }
        #pragma unroll
        for (int nt=0; nt<6; nt++) {
            int wb = GW_HI + (ks*8 + t4)*104 + wn*48 + nt*8 + g8;
            uint32_t bh0 = su[wb],                 bh1 = su[wb + 4*104];
            uint32_t bl0 = su[wb + (GW_LO-GW_HI)], bl1 = su[wb + (GW_LO-GW_HI) + 4*104];
            #pragma unroll
            for (int sub=0; sub<2; sub++) {
                mmab(d[sub][nt], ah[sub], bh0, bh1);
                mmab(d[sub][nt], al[sub], bh0, bh1);
                mmab(d[sub][nt], ah[sub], bl0, bl1);
            }
        }
    }

    // ---- epilogue: frags -> s_out[96 co][132] -> per-mode writes ----
    __syncthreads();
    float* s_out = (float*)su;
    #pragma unroll
    for (int sub=0; sub<2; sub++) {
        int row0 = wm*32 + sub*16 + g8;
        #pragma unroll
        for (int nt=0; nt<6; nt++) {
            int c0 = wn*48 + nt*8 + t4*2;
            s_out[(c0  )*132 + row0]     = d[sub][nt][0];
            s_out[(c0+1)*132 + row0]     = d[sub][nt][1];
            s_out[(c0  )*132 + row0 + 8] = d[sub][nt][2];
            s_out[(c0+1)*132 + row0 + 8] = d[sub][nt][3];
        }
    }
    __syncthreads();

    if constexpr (OUT_MODE == 2) {
        float* ob = out + ((size_t)(b*3 + grp)*4)*SP*24;
        for (int f=t; f<3072; f+=256) {
            int h = f/768, rem = f%768, s = rem/6, u = rem%6;
            int ch = h*24 + u*4;
            float4 r;
            r.x = s_out[(ch  )*132 + s] + bias[co0+ch];
            r.y = s_out[(ch+1)*132 + s] + bias[co0+ch+1];
            r.z = s_out[(ch+2)*132 + s] + bias[co0+ch+2];
            r.w = s_out[(ch+3)*132 + s] + bias[co0+ch+3];
            *(float4*)&ob[((size_t)h*SP + s0 + s)*24 + u*4] = r;
        }
    } else {
        for (int i=t; i<3072; i+=256) {
            int co = i>>5, s4 = (i&31)*4;
            float4 v = *(const float4*)&s_out[co*132 + s4];
            float bb = bias[co];
            v.x += bb; v.y += bb; v.z += bb; v.w += bb;
            size_t o0 = (size_t)(b*NC + co)*SP + s0 + s4;
            if constexpr (OUT_MODE == 1) {
                float4 a0 = *(const float4*)&aux[o0];
                v.x = a0.x/(1.f+expf(-v.x));
                v.y = a0.y/(1.f+expf(-v.y));
                v.z = a0.z/(1.f+expf(-v.z));
                v.w = a0.w/(1.f+expf(-v.w));
            }
            *(float4*)&out[o0] = v;
        }
    }
}

// ---------------- axial attention, all 3 axes in one launch ----------------
__global__ void __launch_bounds__(160) k_attn(const float* __restrict__ qkv, float* __restrict__ osum) {
    __shared__ __align__(16) float sq[3840], sk[3840], sv[3840];   // [h][l][24]
    int axis = blockIdx.y;
    int blk = blockIdx.x;
    int b = blk / 1600, r = blk % 1600, a1 = r/40, a2 = r%40;
    int base, lst;
    if (axis == 0)      { base = a1*ND + a2;     lst = HW; }
    else if (axis == 1) { base = a1*HW + a2;     lst = ND; }
    else                { base = a1*HW + a2*ND;  lst = 1;  }
    int t = threadIdx.x;

    const float* qb = qkv + (size_t)(b*3)*4*SP*24;
    for (int f=t; f<2880; f+=160) {
        int which = f/960, rr = f%960, h = rr/240, r2 = rr%240, l = r2/6, u = r2%6;
        float4 val = *(const float4*)&qb[((size_t)(which*4+h)*SP + base + (size_t)l*lst)*24 + u*4];
        float* dst = (which==0) ? sq : ((which==1) ? sk : sv);
        *(float4*)&dst[h*960 + l*24 + u*4] = val;
    }
    __syncthreads();

    int h = t/40, i = t%40;
    float4 q[6];
    #pragma unroll
    for (int u=0;u<6;u++) q[u] = *(const float4*)&sq[h*960 + i*24 + u*4];

    const float scale = 0.20412414523193154f;
    float S[40];
    float mx = -1e30f;
    #pragma unroll
    for (int j=0;j<40;j++) {
        const float4* kp = (const float4*)&sk[h*960 + j*24];
        float s = 0.f;
        #pragma unroll
        for (int u=0;u<6;u++) {
            float4 kv = kp[u];
            s += q[u].x*kv.x + q[u].y*kv.y + q[u].z*kv.z + q[u].w*kv.w;
        }
        s *= scale;
        S[j] = s;
        mx = fmaxf(mx, s);
    }
    float sum = 0.f;
    #pragma unroll
    for (int j=0;j<40;j++) { S[j] = expf(S[j]-mx); sum += S[j]; }
    float inv = 1.f/sum;

    float4 o[6];
    #pragma unroll
    for (int u=0;u<6;u++) o[u] = make_float4(0.f,0.f,0.f,0.f);
    #pragma unroll
    for (int j=0;j<40;j++) {
        float p = S[j]*inv;
        const float4* vp = (const float4*)&sv[h*960 + j*24];
        #pragma unroll
        for (int u=0;u<6;u++) {
            float4 vv = vp[u];
            o[u].x += p*vv.x; o[u].y += p*vv.y; o[u].z += p*vv.z; o[u].w += p*vv.w;
        }
    }
    size_t ob = (size_t)axis*OSLAB + ((size_t)(b*4+h)*SP + base + (size_t)i*lst)*24;
    #pragma unroll
    for (int u=0;u<6;u++)
        *(float4*)&osum[ob + u*4] = o[u];
}

// ---------------- launch ----------------
extern "C" void kernel_launch(void* const* d_in, const int* in_sizes, int n_in,
                              void* d_out, int out_size) {
    const float* x      = (const float*)d_in[0];
    const float* pos    = (const float*)d_in[1];
    const float* qkv_w  = (const float*)d_in[2];
    const float* qkv_b  = (const float*)d_in[3];
    const float* lp1_w  = (const float*)d_in[4];
    const float* lp1_b  = (const float*)d_in[5];
    const float* lp2_w  = (const float*)d_in[6];
    const float* lp2_b  = (const float*)d_in[7];
    const float* mod1_w = (const float*)d_in[8];
    const float* mod1_b = (const float*)d_in[9];
    const float* mod2_w = (const float*)d_in[10];
    const float* mod2_b = (const float*)d_in[11];
    // d_in[12..16]: pa_w, pa_b, R6_d, R6_h, R6_w — mathematically unused
    const float* proj_w = (const float*)d_in[17];
    const float* proj_b = (const float*)d_in[18];
    float* out = (float*)d_out;

    float *buf1, *buf2, *xmod, *qkvp, *osum;
    cudaGetSymbolAddress((void**)&buf1, g_buf1);
    cudaGetSymbolAddress((void**)&buf2, g_buf2);
    cudaGetSymbolAddress((void**)&xmod, g_xmod);
    cudaGetSymbolAddress((void**)&qkvp, g_qkv);
    cudaGetSymbolAddress((void**)&osum, g_osum);

    const int GS = GEMM_U32 * 4;   // 92160 B dynamic smem for gemms
    const int CS = CONV_U32 * 4;   // 93184 B for conv
    cudaFuncSetAttribute(k_gemm<1,0>, cudaFuncAttributeMaxDynamicSharedMemorySize, GS);
    cudaFuncSetAttribute(k_gemm<0,0>, cudaFuncAttributeMaxDynamicSharedMemorySize, GS);
    cudaFuncSetAttribute(k_gemm<1,1>, cudaFuncAttributeMaxDynamicSharedMemorySize, GS);
    cudaFuncSetAttribute(k_gemm<0,2>, cudaFuncAttributeMaxDynamicSharedMemorySize, GS);
    cudaFuncSetAttribute(k_gemm<2,0>, cudaFuncAttributeMaxDynamicSharedMemorySize, GS);
    cudaFuncSetAttribute(k_conv3_bf16, cudaFuncAttributeMaxDynamicSharedMemorySize, CS);

    // prep: transpose input + bf16 hi/lo split; pack conv weights
    k_xt<<<dim3(1000,3,2), 256>>>(pos);
    k_wprep<<<(27*96*48 + 255)/256, 256>>>(lp1_w);
    // conv3 on tensor cores (3xBF16, writes g_buf1 with bias)
    k_conv3_bf16<<<1000, 256, CS>>>(lp1_b);
    k_stats1<<<dim3(NB*NC,8), 256>>>(buf1);
    k_stats2<<<1, NB*NC>>>();
    k_gemm<1,0><<<dim3(500,1,2), 256, GS>>>(buf1, lp2_w, lp2_b, buf2, nullptr);   // local
    k_gemm<0,0><<<dim3(500,1,2), 256, GS>>>(buf2, mod1_w, mod1_b, buf1, nullptr);
    k_stats1<<<dim3(NB*NC,8), 256>>>(buf1);
    k_stats2<<<1, NB*NC>>>();
    k_gemm<1,1><<<dim3(500,1,2), 256, GS>>>(buf1, mod2_w, mod2_b, xmod, x);       // x_mod
    k_gemm<0,2><<<dim3(500,3,2), 256, GS>>>(xmod, qkv_w, qkv_b, qkvp, nullptr);
    k_attn<<<dim3(3200,3), 160>>>(qkvp, osum);
    k_gemm<2,0><<<dim3(500,1,2), 256, GS>>>(osum, proj_w, proj_b, out, nullptr);
}